// round 1
// baseline (speedup 1.0000x reference)
#include <cuda_runtime.h>
#include <math.h>

#define S 2048
#define D 2048
#define H 16
#define HD 128
#define II 8192
#define EPS 1e-5f

// ---------------- scratch (static device globals; no allocation) ----------
__device__ float g_nx [(size_t)S * D];
__device__ float g_q  [(size_t)S * D];
__device__ float g_k  [(size_t)S * D];
__device__ float g_v  [(size_t)S * D];
__device__ float g_att[(size_t)S * D];
__device__ float g_x1 [(size_t)S * D];
__device__ float g_nx2[(size_t)S * D];
__device__ float g_h1 [(size_t)S * II];
__device__ float g_h3 [(size_t)S * II];
__device__ float g_sc [(size_t)H * S * S];   // 256 MiB attention scores/probs

// ---------------- rmsnorm ------------------------------------------------
__global__ __launch_bounds__(256) void rmsnorm_kernel(
    const float* __restrict__ x, const float* __restrict__ w,
    float* __restrict__ out)
{
    const int row = blockIdx.x;
    const float4* xr = reinterpret_cast<const float4*>(x + (size_t)row * D);
    float4 va[2];
    float ss = 0.f;
#pragma unroll
    for (int i = 0; i < 2; i++) {
        va[i] = xr[threadIdx.x + i * 256];
        ss += va[i].x * va[i].x + va[i].y * va[i].y +
              va[i].z * va[i].z + va[i].w * va[i].w;
    }
    __shared__ float red[256];
    red[threadIdx.x] = ss;
    __syncthreads();
    for (int s = 128; s > 0; s >>= 1) {
        if (threadIdx.x < s) red[threadIdx.x] += red[threadIdx.x + s];
        __syncthreads();
    }
    const float r = rsqrtf(red[0] * (1.0f / D) + EPS);
    const float4* w4 = reinterpret_cast<const float4*>(w);
    float4* o = reinterpret_cast<float4*>(out + (size_t)row * D);
#pragma unroll
    for (int i = 0; i < 2; i++) {
        float4 wv = w4[threadIdx.x + i * 256];
        float4 ov;
        ov.x = va[i].x * r * wv.x;
        ov.y = va[i].y * r * wv.y;
        ov.z = va[i].z * r * wv.z;
        ov.w = va[i].w * r * wv.w;
        o[threadIdx.x + i * 256] = ov;
    }
}

// ---------------- generic tiled SGEMM (NN), optional residual, batched ---
#define BM 128
#define BN 128
#define BK 16
#define TM 8
#define TN 8

__global__ __launch_bounds__(256) void sgemm_nn(
    const float* __restrict__ A, int lda, size_t strideA,
    const float* __restrict__ B, int ldb, size_t strideB,
    const float* __restrict__ Res, int ldres, size_t strideRes,
    float* __restrict__ C, int ldc, size_t strideC,
    int K)
{
    A += (size_t)blockIdx.z * strideA;
    B += (size_t)blockIdx.z * strideB;
    C += (size_t)blockIdx.z * strideC;
    if (Res) Res += (size_t)blockIdx.z * strideRes;

    __shared__ float As[BK][BM + 4];
    __shared__ float Bs[BK][BN];

    const int tid  = threadIdx.x;
    const int row0 = blockIdx.y * BM;
    const int col0 = blockIdx.x * BN;
    const int tx = tid & 15, ty = tid >> 4;

    const int a_r = tid >> 2;          // 0..63 (+64 on 2nd)
    const int a_c = (tid & 3) * 4;     // 0,4,8,12
    const int b_r = tid >> 5;          // 0..7 (+8 on 2nd)
    const int b_c = (tid & 31) * 4;    // 0..124

    float acc[TM][TN] = {};

    for (int k0 = 0; k0 < K; k0 += BK) {
#pragma unroll
        for (int i = 0; i < 2; i++) {
            const int r = a_r + i * 64;
            float4 v = *reinterpret_cast<const float4*>(
                A + (size_t)(row0 + r) * lda + k0 + a_c);
            As[a_c + 0][r] = v.x;
            As[a_c + 1][r] = v.y;
            As[a_c + 2][r] = v.z;
            As[a_c + 3][r] = v.w;
        }
#pragma unroll
        for (int i = 0; i < 2; i++) {
            const int r = b_r + i * 8;
            float4 v = *reinterpret_cast<const float4*>(
                B + (size_t)(k0 + r) * ldb + col0 + b_c);
            *reinterpret_cast<float4*>(&Bs[r][b_c]) = v;
        }
        __syncthreads();
#pragma unroll
        for (int kk = 0; kk < BK; kk++) {
            float ra[TM], rb[TN];
#pragma unroll
            for (int m = 0; m < TM; m++) ra[m] = As[kk][ty * TM + m];
#pragma unroll
            for (int n = 0; n < TN; n++) rb[n] = Bs[kk][tx * TN + n];
#pragma unroll
            for (int m = 0; m < TM; m++)
#pragma unroll
                for (int n = 0; n < TN; n++)
                    acc[m][n] += ra[m] * rb[n];
        }
        __syncthreads();
    }

#pragma unroll
    for (int m = 0; m < TM; m++) {
        const int r = row0 + ty * TM + m;
#pragma unroll
        for (int n = 0; n < TN; n += 4) {
            const int c = col0 + tx * TN + n;
            float4 o = make_float4(acc[m][n], acc[m][n + 1],
                                   acc[m][n + 2], acc[m][n + 3]);
            if (Res) {
                float4 rv = *reinterpret_cast<const float4*>(
                    Res + (size_t)r * ldres + c);
                o.x += rv.x; o.y += rv.y; o.z += rv.z; o.w += rv.w;
            }
            *reinterpret_cast<float4*>(C + (size_t)r * ldc + c) = o;
        }
    }
}

// ---------------- RoPE on q and k ----------------------------------------
__global__ __launch_bounds__(256) void rope_kernel(
    float* __restrict__ q, float* __restrict__ k,
    const float* __restrict__ cs, const float* __restrict__ sn)
{
    const int idx = blockIdx.x * 256 + threadIdx.x;   // over S*D/2
    const int s   = idx / (D / 2);
    const int rem = idx % (D / 2);
    const int h   = rem >> 6;
    const int d   = rem & 63;
    const size_t p0 = (size_t)s * D + h * HD + d;
    const size_t p1 = p0 + 64;
    const float c0 = cs[s * HD + d],      s0 = sn[s * HD + d];
    const float c1 = cs[s * HD + d + 64], s1 = sn[s * HD + d + 64];

    const float q0 = q[p0], q1 = q[p1];
    q[p0] = q0 * c0 - q1 * s0;
    q[p1] = q1 * c1 + q0 * s1;
    const float k0 = k[p0], k1 = k[p1];
    k[p0] = k0 * c0 - k1 * s0;
    k[p1] = k1 * c1 + k0 * s1;
}

// ---------------- per-head QK^T (NT) with scale; skip fully-masked tiles -
__global__ __launch_bounds__(256) void score_kernel(
    const float* __restrict__ Q, const float* __restrict__ Km,
    float* __restrict__ Sc)
{
    const int bx = blockIdx.x, by = blockIdx.y, h = blockIdx.z;
    if (bx > by) return;   // tile entirely above diagonal: never read

    const float* A = Q  + (size_t)h * HD;   // [S, D], lda = D
    const float* B = Km + (size_t)h * HD;
    float* C = Sc + (size_t)h * S * S;

    __shared__ float As[BK][BM + 4];
    __shared__ float Bs[BK][BN + 4];

    const int tid  = threadIdx.x;
    const int row0 = by * BM;
    const int col0 = bx * BN;
    const int tx = tid & 15, ty = tid >> 4;
    const int a_r = tid >> 2;
    const int a_c = (tid & 3) * 4;

    float acc[TM][TN] = {};

    for (int k0 = 0; k0 < HD; k0 += BK) {
#pragma unroll
        for (int i = 0; i < 2; i++) {
            const int r = a_r + i * 64;
            float4 va = *reinterpret_cast<const float4*>(
                A + (size_t)(row0 + r) * D + k0 + a_c);
            As[a_c + 0][r] = va.x; As[a_c + 1][r] = va.y;
            As[a_c + 2][r] = va.z; As[a_c + 3][r] = va.w;
            float4 vb = *reinterpret_cast<const float4*>(
                B + (size_t)(col0 + r) * D + k0 + a_c);
            Bs[a_c + 0][r] = vb.x; Bs[a_c + 1][r] = vb.y;
            Bs[a_c + 2][r] = vb.z; Bs[a_c + 3][r] = vb.w;
        }
        __syncthreads();
#pragma unroll
        for (int kk = 0; kk < BK; kk++) {
            float ra[TM], rb[TN];
#pragma unroll
            for (int m = 0; m < TM; m++) ra[m] = As[kk][ty * TM + m];
#pragma unroll
            for (int n = 0; n < TN; n++) rb[n] = Bs[kk][tx * TN + n];
#pragma unroll
            for (int m = 0; m < TM; m++)
#pragma unroll
                for (int n = 0; n < TN; n++)
                    acc[m][n] += ra[m] * rb[n];
        }
        __syncthreads();
    }

    const float scale = 0.08838834764831845f;  // 1/sqrt(128)
#pragma unroll
    for (int m = 0; m < TM; m++) {
        const int r = row0 + ty * TM + m;
#pragma unroll
        for (int n = 0; n < TN; n += 4) {
            const int c = col0 + tx * TN + n;
            float4 o = make_float4(acc[m][n] * scale, acc[m][n + 1] * scale,
                                   acc[m][n + 2] * scale, acc[m][n + 3] * scale);
            *reinterpret_cast<float4*>(C + (size_t)r * S + c) = o;
        }
    }
}

// ---------------- causal softmax (zeros above diagonal) -------------------
__global__ __launch_bounds__(256) void softmax_kernel(float* __restrict__ sc)
{
    const int i = blockIdx.x, h = blockIdx.y;
    float* row = sc + ((size_t)h * S + i) * S;
    const int n = i + 1;

    float vals[8];
    int cnt = 0;
    float mx = -1e30f;
    for (int j = threadIdx.x; j < n; j += 256) {
        const float v = row[j];
        vals[cnt++] = v;
        mx = fmaxf(mx, v);
    }
    __shared__ float red[256];
    red[threadIdx.x] = mx;
    __syncthreads();
    for (int s = 128; s > 0; s >>= 1) {
        if (threadIdx.x < s) red[threadIdx.x] = fmaxf(red[threadIdx.x], red[threadIdx.x + s]);
        __syncthreads();
    }
    mx = red[0];
    __syncthreads();

    float sum = 0.f;
    for (int c = 0; c < cnt; c++) {
        vals[c] = __expf(vals[c] - mx);
        sum += vals[c];
    }
    red[threadIdx.x] = sum;
    __syncthreads();
    for (int s = 128; s > 0; s >>= 1) {
        if (threadIdx.x < s) red[threadIdx.x] += red[threadIdx.x + s];
        __syncthreads();
    }
    const float inv = 1.f / red[0];

    cnt = 0;
    for (int j = threadIdx.x; j < S; j += 256)
        row[j] = (j < n) ? vals[cnt++] * inv : 0.f;
}

// ---------------- silu(h1) * h3 -------------------------------------------
__global__ __launch_bounds__(256) void silu_mul_kernel(
    float* __restrict__ h1, const float* __restrict__ h3)
{
    const size_t idx = (size_t)blockIdx.x * 256 + threadIdx.x;  // over S*II/4
    float4 a = reinterpret_cast<float4*>(h1)[idx];
    const float4 b = reinterpret_cast<const float4*>(h3)[idx];
    a.x = a.x / (1.f + __expf(-a.x)) * b.x;
    a.y = a.y / (1.f + __expf(-a.y)) * b.y;
    a.z = a.z / (1.f + __expf(-a.z)) * b.z;
    a.w = a.w / (1.f + __expf(-a.w)) * b.w;
    reinterpret_cast<float4*>(h1)[idx] = a;
}

// ---------------- launch ---------------------------------------------------
extern "C" void kernel_launch(void* const* d_in, const int* in_sizes, int n_in,
                              void* d_out, int out_size)
{
    const float* x    = (const float*)d_in[0];
    // d_in[1] = attention_mask (exact causal; applied analytically)
    const float* fcos = (const float*)d_in[2];
    const float* fsin = (const float*)d_in[3];
    const float* wq   = (const float*)d_in[4];
    const float* wk   = (const float*)d_in[5];
    const float* wv   = (const float*)d_in[6];
    const float* wo   = (const float*)d_in[7];
    const float* w1   = (const float*)d_in[8];
    const float* w2   = (const float*)d_in[9];
    const float* w3   = (const float*)d_in[10];
    const float* anw  = (const float*)d_in[11];
    const float* fnw  = (const float*)d_in[12];
    float* out = (float*)d_out;

    float *nx, *q, *k, *v, *att, *x1, *nx2, *h1, *h3, *sc;
    cudaGetSymbolAddress((void**)&nx,  g_nx);
    cudaGetSymbolAddress((void**)&q,   g_q);
    cudaGetSymbolAddress((void**)&k,   g_k);
    cudaGetSymbolAddress((void**)&v,   g_v);
    cudaGetSymbolAddress((void**)&att, g_att);
    cudaGetSymbolAddress((void**)&x1,  g_x1);
    cudaGetSymbolAddress((void**)&nx2, g_nx2);
    cudaGetSymbolAddress((void**)&h1,  g_h1);
    cudaGetSymbolAddress((void**)&h3,  g_h3);
    cudaGetSymbolAddress((void**)&sc,  g_sc);

    const dim3 gProj(D / BN, S / BM);        // 16x16
    const dim3 gFfn (II / BN, S / BM);       // 64x16
    const dim3 gSc  (S / BN, S / BM, H);     // 16x16x16
    const dim3 gPv  (HD / BN, S / BM, H);    // 1x16x16

    // attn norm
    rmsnorm_kernel<<<S, 256>>>(x, anw, nx);
    // q,k,v projections
    sgemm_nn<<<gProj, 256>>>(nx, D, 0, wq, D, 0, nullptr, 0, 0, q, D, 0, D);
    sgemm_nn<<<gProj, 256>>>(nx, D, 0, wk, D, 0, nullptr, 0, 0, k, D, 0, D);
    sgemm_nn<<<gProj, 256>>>(nx, D, 0, wv, D, 0, nullptr, 0, 0, v, D, 0, D);
    // rope
    rope_kernel<<<(S * D / 2) / 256, 256>>>(q, k, fcos, fsin);
    // scores = q k^T / sqrt(hd) (per head)
    score_kernel<<<gSc, 256>>>(q, k, sc);
    // causal softmax
    softmax_kernel<<<dim3(S, H), 256>>>(sc);
    // att = P @ V (per head)
    sgemm_nn<<<gPv, 256>>>(sc, S, (size_t)S * S,
                           v, D, (size_t)HD,
                           nullptr, 0, 0,
                           att, D, (size_t)HD, S);
    // out proj + residual
    sgemm_nn<<<gProj, 256>>>(att, D, 0, wo, D, 0, x, D, 0, x1, D, 0, D);
    // ffn norm
    rmsnorm_kernel<<<S, 256>>>(x1, fnw, nx2);
    // gate / up
    sgemm_nn<<<gFfn, 256>>>(nx2, D, 0, w1, II, 0, nullptr, 0, 0, h1, II, 0, D);
    sgemm_nn<<<gFfn, 256>>>(nx2, D, 0, w3, II, 0, nullptr, 0, 0, h3, II, 0, D);
    // silu * gate
    silu_mul_kernel<<<(S * (size_t)II / 4) / 256, 256>>>(h1, h3);
    // down proj + residual -> output
    sgemm_nn<<<gProj, 256>>>(h1, II, 0, w2, D, 0, x1, D, 0, out, D, 0, II);
}

// round 3
// speedup vs baseline: 1.9733x; 1.9733x over previous
#include <cuda_runtime.h>
#include <cuda_bf16.h>
#include <stdint.h>
#include <math.h>

#define S 2048
#define D 2048
#define H 16
#define HD 128
#define II 8192
#define EPS 1e-5f

// ---------------- scratch (static device globals; no allocation) ----------
__device__ float g_nx [(size_t)S * D];
__device__ float g_q  [(size_t)S * D];
__device__ float g_k  [(size_t)S * D];
__device__ float g_v  [(size_t)S * D];
__device__ float g_att[(size_t)S * D];
__device__ float g_x1 [(size_t)S * D];
__device__ float g_nx2[(size_t)S * D];
__device__ float g_h1 [(size_t)S * II];
__device__ float g_h3 [(size_t)S * II];
__device__ float g_sc [(size_t)H * S * S];   // 256 MiB attention scores/probs

// ---------------- helpers --------------------------------------------------
__device__ __forceinline__ void ldm4(unsigned int* r, const __nv_bfloat16* p)
{
    unsigned int a = (unsigned int)__cvta_generic_to_shared((const void*)p);
    asm volatile("ldmatrix.sync.aligned.m8n8.x4.shared.b16 {%0,%1,%2,%3},[%4];"
                 : "=r"(r[0]), "=r"(r[1]), "=r"(r[2]), "=r"(r[3]) : "r"(a));
}

__device__ __forceinline__ void ldm4t(unsigned int* r, const __nv_bfloat16* p)
{
    unsigned int a = (unsigned int)__cvta_generic_to_shared((const void*)p);
    asm volatile("ldmatrix.sync.aligned.m8n8.x4.trans.shared.b16 {%0,%1,%2,%3},[%4];"
                 : "=r"(r[0]), "=r"(r[1]), "=r"(r[2]), "=r"(r[3]) : "r"(a));
}

__device__ __forceinline__ void mma16816(float* d, const unsigned int* a,
                                         const unsigned int* b)
{
    asm volatile(
        "mma.sync.aligned.m16n8k16.row.col.f32.bf16.bf16.f32 "
        "{%0,%1,%2,%3},{%4,%5,%6,%7},{%8,%9},{%0,%1,%2,%3};"
        : "+f"(d[0]), "+f"(d[1]), "+f"(d[2]), "+f"(d[3])
        : "r"(a[0]), "r"(a[1]), "r"(a[2]), "r"(a[3]), "r"(b[0]), "r"(b[1]));
}

__device__ __forceinline__ void split_store(__nv_bfloat16* hi, __nv_bfloat16* lo,
                                            int idx, float x0, float x1)
{
    __nv_bfloat16 h0 = __float2bfloat16_rn(x0);
    __nv_bfloat16 h1 = __float2bfloat16_rn(x1);
    __nv_bfloat16 l0 = __float2bfloat16_rn(x0 - __bfloat162float(h0));
    __nv_bfloat16 l1 = __float2bfloat16_rn(x1 - __bfloat162float(h1));
    *reinterpret_cast<__nv_bfloat162*>(hi + idx) = __halves2bfloat162(h0, h1);
    *reinterpret_cast<__nv_bfloat162*>(lo + idx) = __halves2bfloat162(l0, l1);
}

#define LDA_S 40     // 128x32 A/B-NT tile, padded row stride (halves)
#define LDB_S 136    // 32x128 B-NN tile, padded row stride (halves)

// ---------------- bf16x3 GEMM, NN variant ---------------------------------
// C[M,N] = A[M,K] * B[K,N] (+Res) * scale.  Batched over blockIdx.z.
// causalK != 0: limit K to (blockIdx.y+1)*128 (PV with causal probs).
__global__ __launch_bounds__(256) void gemm3_nn(
    const float* __restrict__ A, int lda, size_t sA,
    const float* __restrict__ B, int ldb, size_t sB,
    const float* __restrict__ Res, int ldres, size_t sRes,
    float* __restrict__ C, int ldc, size_t sC,
    int K, int causalK, float scale)
{
    A += (size_t)blockIdx.z * sA;
    B += (size_t)blockIdx.z * sB;
    C += (size_t)blockIdx.z * sC;
    if (Res) Res += (size_t)blockIdx.z * sRes;

    __shared__ __nv_bfloat16 sAh[128 * LDA_S], sAl[128 * LDA_S];
    __shared__ __nv_bfloat16 sBh[32 * LDB_S],  sBl[32 * LDB_S];

    const int tid  = threadIdx.x;
    const int lane = tid & 31;
    const int warp = tid >> 5;
    const int wm   = warp >> 1;
    const int wn   = warp & 1;
    const int row0 = blockIdx.y * 128;
    const int col0 = blockIdx.x * 128;

    const int ar = tid >> 1;           // 0..127
    const int aq = (tid & 1) * 16;     // 0/16
    const int br = tid >> 3;           // 0..31
    const int bq = (tid & 7) * 16;     // 0..112

    const int kEnd = causalK ? min(K, (int)(blockIdx.y + 1) * 128) : K;

    float acc[2][8][4];
#pragma unroll
    for (int m = 0; m < 2; m++)
#pragma unroll
        for (int n = 0; n < 8; n++)
#pragma unroll
            for (int i = 0; i < 4; i++) acc[m][n][i] = 0.f;

    float4 aReg[4], bReg[4];
#pragma unroll
    for (int j = 0; j < 4; j++)
        aReg[j] = *reinterpret_cast<const float4*>(
            A + (size_t)(row0 + ar) * lda + aq + j * 4);
#pragma unroll
    for (int j = 0; j < 4; j++)
        bReg[j] = *reinterpret_cast<const float4*>(
            B + (size_t)br * ldb + col0 + bq + j * 4);

    for (int k0 = 0; k0 < kEnd; k0 += 32) {
#pragma unroll
        for (int j = 0; j < 4; j++) {
            const int ai = ar * LDA_S + aq + j * 4;
            split_store(sAh, sAl, ai,     aReg[j].x, aReg[j].y);
            split_store(sAh, sAl, ai + 2, aReg[j].z, aReg[j].w);
        }
#pragma unroll
        for (int j = 0; j < 4; j++) {
            const int bi = br * LDB_S + bq + j * 4;
            split_store(sBh, sBl, bi,     bReg[j].x, bReg[j].y);
            split_store(sBh, sBl, bi + 2, bReg[j].z, bReg[j].w);
        }
        __syncthreads();

        const int kn = k0 + 32;
        if (kn < kEnd) {
#pragma unroll
            for (int j = 0; j < 4; j++)
                aReg[j] = *reinterpret_cast<const float4*>(
                    A + (size_t)(row0 + ar) * lda + kn + aq + j * 4);
#pragma unroll
            for (int j = 0; j < 4; j++)
                bReg[j] = *reinterpret_cast<const float4*>(
                    B + (size_t)(kn + br) * ldb + col0 + bq + j * 4);
        }

#pragma unroll
        for (int kk = 0; kk < 32; kk += 16) {
            unsigned int ah[2][4], al[2][4];
#pragma unroll
            for (int mt = 0; mt < 2; mt++) {
                const int off = (wm * 32 + mt * 16 + (lane & 15)) * LDA_S
                              + kk + (lane >> 4) * 8;
                ldm4(ah[mt], sAh + off);
                ldm4(al[mt], sAl + off);
            }
            unsigned int bh[8][2], bl[8][2];
#pragma unroll
            for (int g = 0; g < 4; g++) {
                const int off = (kk + (lane & 15)) * LDB_S
                              + wn * 64 + g * 16 + (lane >> 4) * 8;
                unsigned int r[4];
                ldm4t(r, sBh + off);
                bh[2 * g][0] = r[0]; bh[2 * g][1] = r[1];
                bh[2 * g + 1][0] = r[2]; bh[2 * g + 1][1] = r[3];
                ldm4t(r, sBl + off);
                bl[2 * g][0] = r[0]; bl[2 * g][1] = r[1];
                bl[2 * g + 1][0] = r[2]; bl[2 * g + 1][1] = r[3];
            }
#pragma unroll
            for (int mt = 0; mt < 2; mt++)
#pragma unroll
                for (int nt = 0; nt < 8; nt++) {
                    mma16816(acc[mt][nt], ah[mt], bh[nt]);
                    mma16816(acc[mt][nt], al[mt], bh[nt]);
                    mma16816(acc[mt][nt], ah[mt], bl[nt]);
                }
        }
        __syncthreads();
    }

#pragma unroll
    for (int mt = 0; mt < 2; mt++) {
        const int r0 = row0 + wm * 32 + mt * 16 + (lane >> 2);
#pragma unroll
        for (int nt = 0; nt < 8; nt++) {
            const int c = col0 + wn * 64 + nt * 8 + (lane & 3) * 2;
            float2 v0 = make_float2(acc[mt][nt][0] * scale, acc[mt][nt][1] * scale);
            float2 v1 = make_float2(acc[mt][nt][2] * scale, acc[mt][nt][3] * scale);
            if (Res) {
                float2 q0 = *reinterpret_cast<const float2*>(
                    Res + (size_t)r0 * ldres + c);
                float2 q1 = *reinterpret_cast<const float2*>(
                    Res + (size_t)(r0 + 8) * ldres + c);
                v0.x += q0.x; v0.y += q0.y; v1.x += q1.x; v1.y += q1.y;
            }
            *reinterpret_cast<float2*>(C + (size_t)r0 * ldc + c) = v0;
            *reinterpret_cast<float2*>(C + (size_t)(r0 + 8) * ldc + c) = v1;
        }
    }
}

// ---------------- bf16x3 GEMM, NT variant (scores) ------------------------
// C[M,N] = A[M,K] * B[N,K]^T * scale. causal: skip blocks above diagonal.
__global__ __launch_bounds__(256) void gemm3_nt(
    const float* __restrict__ A, int lda, size_t sA,
    const float* __restrict__ B, int ldb, size_t sB,
    float* __restrict__ C, int ldc, size_t sC,
    int K, float scale)
{
    if (blockIdx.x > blockIdx.y) return;   // causal block skip

    A += (size_t)blockIdx.z * sA;
    B += (size_t)blockIdx.z * sB;
    C += (size_t)blockIdx.z * sC;

    __shared__ __nv_bfloat16 sAh[128 * LDA_S], sAl[128 * LDA_S];
    __shared__ __nv_bfloat16 sBh[128 * LDA_S], sBl[128 * LDA_S];

    const int tid  = threadIdx.x;
    const int lane = tid & 31;
    const int warp = tid >> 5;
    const int wm   = warp >> 1;
    const int wn   = warp & 1;
    const int row0 = blockIdx.y * 128;
    const int col0 = blockIdx.x * 128;

    const int ar = tid >> 1;
    const int aq = (tid & 1) * 16;

    float acc[2][8][4];
#pragma unroll
    for (int m = 0; m < 2; m++)
#pragma unroll
        for (int n = 0; n < 8; n++)
#pragma unroll
            for (int i = 0; i < 4; i++) acc[m][n][i] = 0.f;

    float4 aReg[4], bReg[4];
#pragma unroll
    for (int j = 0; j < 4; j++) {
        aReg[j] = *reinterpret_cast<const float4*>(
            A + (size_t)(row0 + ar) * lda + aq + j * 4);
        bReg[j] = *reinterpret_cast<const float4*>(
            B + (size_t)(col0 + ar) * ldb + aq + j * 4);
    }

    for (int k0 = 0; k0 < K; k0 += 32) {
#pragma unroll
        for (int j = 0; j < 4; j++) {
            const int i0 = ar * LDA_S + aq + j * 4;
            split_store(sAh, sAl, i0,     aReg[j].x, aReg[j].y);
            split_store(sAh, sAl, i0 + 2, aReg[j].z, aReg[j].w);
            split_store(sBh, sBl, i0,     bReg[j].x, bReg[j].y);
            split_store(sBh, sBl, i0 + 2, bReg[j].z, bReg[j].w);
        }
        __syncthreads();

        const int kn = k0 + 32;
        if (kn < K) {
#pragma unroll
            for (int j = 0; j < 4; j++) {
                aReg[j] = *reinterpret_cast<const float4*>(
                    A + (size_t)(row0 + ar) * lda + kn + aq + j * 4);
                bReg[j] = *reinterpret_cast<const float4*>(
                    B + (size_t)(col0 + ar) * ldb + kn + aq + j * 4);
            }
        }

#pragma unroll
        for (int kk = 0; kk < 32; kk += 16) {
            unsigned int ah[2][4], al[2][4];
#pragma unroll
            for (int mt = 0; mt < 2; mt++) {
                const int off = (wm * 32 + mt * 16 + (lane & 15)) * LDA_S
                              + kk + (lane >> 4) * 8;
                ldm4(ah[mt], sAh + off);
                ldm4(al[mt], sAl + off);
            }
            unsigned int bh[8][2], bl[8][2];
#pragma unroll
            for (int g = 0; g < 4; g++) {
                const int off = (wn * 64 + g * 16 + (lane & 15)) * LDA_S
                              + kk + (lane >> 4) * 8;
                unsigned int r[4];
                ldm4(r, sBh + off);
                bh[2 * g][0] = r[0]; bh[2 * g][1] = r[2];
                bh[2 * g + 1][0] = r[1]; bh[2 * g + 1][1] = r[3];
                ldm4(r, sBl + off);
                bl[2 * g][0] = r[0]; bl[2 * g][1] = r[2];
                bl[2 * g + 1][0] = r[1]; bl[2 * g + 1][1] = r[3];
            }
#pragma unroll
            for (int mt = 0; mt < 2; mt++)
#pragma unroll
                for (int nt = 0; nt < 8; nt++) {
                    mma16816(acc[mt][nt], ah[mt], bh[nt]);
                    mma16816(acc[mt][nt], al[mt], bh[nt]);
                    mma16816(acc[mt][nt], ah[mt], bl[nt]);
                }
        }
        __syncthreads();
    }

#pragma unroll
    for (int mt = 0; mt < 2; mt++) {
        const int r0 = row0 + wm * 32 + mt * 16 + (lane >> 2);
#pragma unroll
        for (int nt = 0; nt < 8; nt++) {
            const int c = col0 + wn * 64 + nt * 8 + (lane & 3) * 2;
            float2 v0 = make_float2(acc[mt][nt][0] * scale, acc[mt][nt][1] * scale);
            float2 v1 = make_float2(acc[mt][nt][2] * scale, acc[mt][nt][3] * scale);
            *reinterpret_cast<float2*>(C + (size_t)r0 * ldc + c) = v0;
            *reinterpret_cast<float2*>(C + (size_t)(r0 + 8) * ldc + c) = v1;
        }
    }
}

// ---------------- rmsnorm ------------------------------------------------
__global__ __launch_bounds__(256) void rmsnorm_kernel(
    const float* __restrict__ x, const float* __restrict__ w,
    float* __restrict__ out)
{
    const int row = blockIdx.x;
    const float4* xr = reinterpret_cast<const float4*>(x + (size_t)row * D);
    float4 va[2];
    float ss = 0.f;
#pragma unroll
    for (int i = 0; i < 2; i++) {
        va[i] = xr[threadIdx.x + i * 256];
        ss += va[i].x * va[i].x + va[i].y * va[i].y +
              va[i].z * va[i].z + va[i].w * va[i].w;
    }
    __shared__ float red[256];
    red[threadIdx.x] = ss;
    __syncthreads();
    for (int s = 128; s > 0; s >>= 1) {
        if (threadIdx.x < s) red[threadIdx.x] += red[threadIdx.x + s];
        __syncthreads();
    }
    const float r = rsqrtf(red[0] * (1.0f / D) + EPS);
    const float4* w4 = reinterpret_cast<const float4*>(w);
    float4* o = reinterpret_cast<float4*>(out + (size_t)row * D);
#pragma unroll
    for (int i = 0; i < 2; i++) {
        float4 wv = w4[threadIdx.x + i * 256];
        float4 ov;
        ov.x = va[i].x * r * wv.x;
        ov.y = va[i].y * r * wv.y;
        ov.z = va[i].z * r * wv.z;
        ov.w = va[i].w * r * wv.w;
        o[threadIdx.x + i * 256] = ov;
    }
}

// ---------------- RoPE on q and k ----------------------------------------
__global__ __launch_bounds__(256) void rope_kernel(
    float* __restrict__ q, float* __restrict__ k,
    const float* __restrict__ cs, const float* __restrict__ sn)
{
    const int idx = blockIdx.x * 256 + threadIdx.x;   // over S*D/2
    const int s   = idx / (D / 2);
    const int rem = idx % (D / 2);
    const int h   = rem >> 6;
    const int d   = rem & 63;
    const size_t p0 = (size_t)s * D + h * HD + d;
    const size_t p1 = p0 + 64;
    const float c0 = cs[s * HD + d],      s0 = sn[s * HD + d];
    const float c1 = cs[s * HD + d + 64], s1 = sn[s * HD + d + 64];

    const float q0 = q[p0], q1 = q[p1];
    q[p0] = q0 * c0 - q1 * s0;
    q[p1] = q1 * c1 + q0 * s1;
    const float k0 = k[p0], k1 = k[p1];
    k[p0] = k0 * c0 - k1 * s0;
    k[p1] = k1 * c1 + k0 * s1;
}

// ---------------- causal softmax (zeros above diagonal) -------------------
__global__ __launch_bounds__(256) void softmax_kernel(float* __restrict__ sc)
{
    const int i = blockIdx.x, h = blockIdx.y;
    float* row = sc + ((size_t)h * S + i) * S;
    const int n = i + 1;

    float vals[8];
    int cnt = 0;
    float mx = -1e30f;
    for (int j = threadIdx.x; j < n; j += 256) {
        const float v = row[j];
        vals[cnt++] = v;
        mx = fmaxf(mx, v);
    }
    __shared__ float red[256];
    red[threadIdx.x] = mx;
    __syncthreads();
    for (int s = 128; s > 0; s >>= 1) {
        if (threadIdx.x < s)
            red[threadIdx.x] = fmaxf(red[threadIdx.x], red[threadIdx.x + s]);
        __syncthreads();
    }
    mx = red[0];
    __syncthreads();

    float sum = 0.f;
    for (int c = 0; c < cnt; c++) {
        vals[c] = __expf(vals[c] - mx);
        sum += vals[c];
    }
    red[threadIdx.x] = sum;
    __syncthreads();
    for (int s = 128; s > 0; s >>= 1) {
        if (threadIdx.x < s) red[threadIdx.x] += red[threadIdx.x + s];
        __syncthreads();
    }
    const float inv = 1.f / red[0];

    cnt = 0;
    for (int j = threadIdx.x; j < S; j += 256)
        row[j] = (j < n) ? vals[cnt++] * inv : 0.f;
}

// ---------------- silu(h1) * h3 -------------------------------------------
__global__ __launch_bounds__(256) void silu_mul_kernel(
    float* __restrict__ h1, const float* __restrict__ h3)
{
    const size_t idx = (size_t)blockIdx.x * 256 + threadIdx.x;  // over S*II/4
    float4 a = reinterpret_cast<float4*>(h1)[idx];
    const float4 b = reinterpret_cast<const float4*>(h3)[idx];
    a.x = a.x / (1.f + __expf(-a.x)) * b.x;
    a.y = a.y / (1.f + __expf(-a.y)) * b.y;
    a.z = a.z / (1.f + __expf(-a.z)) * b.z;
    a.w = a.w / (1.f + __expf(-a.w)) * b.w;
    reinterpret_cast<float4*>(h1)[idx] = a;
}

// ---------------- launch ---------------------------------------------------
extern "C" void kernel_launch(void* const* d_in, const int* in_sizes, int n_in,
                              void* d_out, int out_size)
{
    const float* x    = (const float*)d_in[0];
    // d_in[1] = attention_mask (exact causal; applied analytically)
    const float* fcos = (const float*)d_in[2];
    const float* fsin = (const float*)d_in[3];
    const float* wq   = (const float*)d_in[4];
    const float* wk   = (const float*)d_in[5];
    const float* wv   = (const float*)d_in[6];
    const float* wo   = (const float*)d_in[7];
    const float* w1   = (const float*)d_in[8];
    const float* w2   = (const float*)d_in[9];
    const float* w3   = (const float*)d_in[10];
    const float* anw  = (const float*)d_in[11];
    const float* fnw  = (const float*)d_in[12];
    float* out = (float*)d_out;

    float *nx, *q, *k, *v, *att, *x1, *nx2, *h1, *h3, *sc;
    cudaGetSymbolAddress((void**)&nx,  g_nx);
    cudaGetSymbolAddress((void**)&q,   g_q);
    cudaGetSymbolAddress((void**)&k,   g_k);
    cudaGetSymbolAddress((void**)&v,   g_v);
    cudaGetSymbolAddress((void**)&att, g_att);
    cudaGetSymbolAddress((void**)&x1,  g_x1);
    cudaGetSymbolAddress((void**)&nx2, g_nx2);
    cudaGetSymbolAddress((void**)&h1,  g_h1);
    cudaGetSymbolAddress((void**)&h3,  g_h3);
    cudaGetSymbolAddress((void**)&sc,  g_sc);

    const dim3 gProj(D / 128, S / 128);        // 16x16
    const dim3 gFfn (II / 128, S / 128);       // 64x16
    const dim3 gSc  (S / 128, S / 128, H);     // 16x16x16
    const dim3 gPv  (HD / 128, S / 128, H);    // 1x16x16

    const float iscale = 0.08838834764831845f; // 1/sqrt(128)

    rmsnorm_kernel<<<S, 256>>>(x, anw, nx);

    gemm3_nn<<<gProj, 256>>>(nx, D, 0, wq, D, 0, nullptr, 0, 0,
                             q, D, 0, D, 0, 1.f);
    gemm3_nn<<<gProj, 256>>>(nx, D, 0, wk, D, 0, nullptr, 0, 0,
                             k, D, 0, D, 0, 1.f);
    gemm3_nn<<<gProj, 256>>>(nx, D, 0, wv, D, 0, nullptr, 0, 0,
                             v, D, 0, D, 0, 1.f);

    rope_kernel<<<(S * D / 2) / 256, 256>>>(q, k, fcos, fsin);

    gemm3_nt<<<gSc, 256>>>(q, D, HD, k, D, HD,
                           sc, S, (size_t)S * S, HD, iscale);

    softmax_kernel<<<dim3(S, H), 256>>>(sc);

    gemm3_nn<<<gPv, 256>>>(sc, S, (size_t)S * S, v, D, HD, nullptr, 0, 0,
                           att, D, HD, S, 1, 1.f);

    gemm3_nn<<<gProj, 256>>>(att, D, 0, wo, D, 0, x, D, 0,
                             x1, D, 0, D, 0, 1.f);

    rmsnorm_kernel<<<S, 256>>>(x1, fnw, nx2);

    gemm3_nn<<<gFfn, 256>>>(nx2, D, 0, w1, II, 0, nullptr, 0, 0,
                            h1, II, 0, D, 0, 1.f);
    gemm3_nn<<<gFfn, 256>>>(nx2, D, 0, w3, II, 0, nullptr, 0, 0,
                            h3, II, 0, D, 0, 1.f);

    silu_mul_kernel<<<(S * (size_t)II / 4) / 256, 256>>>(h1, h3);

    gemm3_nn<<<gProj, 256>>>(h1, II, 0, w2, D, 0, x1, D, 0,
                             out, D, 0, II, 0, 1.f);
}

// round 5
// speedup vs baseline: 2.5267x; 1.2804x over previous
#include <cuda_runtime.h>
#include <cuda_bf16.h>
#include <stdint.h>
#include <math.h>

#define S 2048
#define D 2048
#define H 16
#define HD 128
#define II 8192
#define EPS 1e-5f

typedef __nv_bfloat16 bf16;
typedef __nv_bfloat162 bf162;

// ---------------- scratch (static device globals; no allocation) ----------
// fp32 intermediates
__device__ float g_qf [(size_t)S * D];
__device__ float g_kf [(size_t)S * D];
__device__ float g_x1 [(size_t)S * D];
__device__ float g_h1 [(size_t)S * II];
__device__ float g_h3 [(size_t)S * II];
__device__ float g_sc [(size_t)H * S * S];
// bf16 hi/lo split operands
__device__ bf16 g_nxh [(size_t)S * D],  g_nxl [(size_t)S * D];
__device__ bf16 g_qh  [(size_t)S * D],  g_ql  [(size_t)S * D];
__device__ bf16 g_kh  [(size_t)S * D],  g_kl  [(size_t)S * D];
__device__ bf16 g_vh  [(size_t)S * D],  g_vl  [(size_t)S * D];
__device__ bf16 g_ath [(size_t)S * D],  g_atl [(size_t)S * D];
__device__ bf16 g_nx2h[(size_t)S * D],  g_nx2l[(size_t)S * D];
__device__ bf16 g_gh  [(size_t)S * II], g_gl  [(size_t)S * II];
__device__ bf16 g_ph  [(size_t)H * S * S], g_pl [(size_t)H * S * S];
__device__ bf16 g_wqh [(size_t)D * D],  g_wql [(size_t)D * D];
__device__ bf16 g_wkh [(size_t)D * D],  g_wkl [(size_t)D * D];
__device__ bf16 g_wvh [(size_t)D * D],  g_wvl [(size_t)D * D];
__device__ bf16 g_woh [(size_t)D * D],  g_wol [(size_t)D * D];
__device__ bf16 g_w1h [(size_t)D * II], g_w1l [(size_t)D * II];
__device__ bf16 g_w3h [(size_t)D * II], g_w3l [(size_t)D * II];
__device__ bf16 g_w2h [(size_t)II * D], g_w2l [(size_t)II * D];

// ---------------- PTX helpers ---------------------------------------------
__device__ __forceinline__ uint32_t smem_u32(const void* p)
{
    uint32_t a;
    asm("{ .reg .u64 t; cvta.to.shared.u64 t, %1; cvt.u32.u64 %0, t; }"
        : "=r"(a) : "l"(p));
    return a;
}

__device__ __forceinline__ void cpa16(uint32_t dst, const void* src)
{
    asm volatile("cp.async.cg.shared.global [%0], [%1], 16;"
                 :: "r"(dst), "l"(src));
}
#define CPA_COMMIT() asm volatile("cp.async.commit_group;" ::: "memory")
#define CPA_WAIT(n)  asm volatile("cp.async.wait_group %0;" :: "n"(n) : "memory")

__device__ __forceinline__ void ldm4u(unsigned int* r, uint32_t a)
{
    asm volatile("ldmatrix.sync.aligned.m8n8.x4.shared.b16 {%0,%1,%2,%3},[%4];"
                 : "=r"(r[0]), "=r"(r[1]), "=r"(r[2]), "=r"(r[3]) : "r"(a));
}
__device__ __forceinline__ void ldm4tu(unsigned int* r, uint32_t a)
{
    asm volatile("ldmatrix.sync.aligned.m8n8.x4.trans.shared.b16 {%0,%1,%2,%3},[%4];"
                 : "=r"(r[0]), "=r"(r[1]), "=r"(r[2]), "=r"(r[3]) : "r"(a));
}
__device__ __forceinline__ void mma16816(float* d, const unsigned int* a,
                                         const unsigned int* b)
{
    asm volatile(
        "mma.sync.aligned.m16n8k16.row.col.f32.bf16.bf16.f32 "
        "{%0,%1,%2,%3},{%4,%5,%6,%7},{%8,%9},{%0,%1,%2,%3};"
        : "+f"(d[0]), "+f"(d[1]), "+f"(d[2]), "+f"(d[3])
        : "r"(a[0]), "r"(a[1]), "r"(a[2]), "r"(a[3]), "r"(b[0]), "r"(b[1]));
}

__device__ __forceinline__ void split1(float x, bf16* h, bf16* l)
{
    bf16 hh = __float2bfloat16_rn(x);
    *h = hh;
    *l = __float2bfloat16_rn(x - __bfloat162float(hh));
}

// ---------------- bf16x3 GEMM on mma.sync, cp.async 3-stage pipeline ------
// C = A * op(B) (+Res) * scale. A/B are pre-split bf16 hi/lo in gmem.
// ntB=1: B is [N,K] (k-contiguous). ntB=0: B is [K,N].
// causal=1: skip blocks above diagonal. causal=2: limit K per row block.
// Out: Cf fp32 (res+scale) if non-null, else (Ch, Cl) bf16 split.
// SMEM stage (32KB): Ah[8K] Al[8K] Bh[8K] Bl[8K]; 3 stages = 96KB.
#define STG_SZ 32768
#define SMEM_SZ (3 * STG_SZ)

__device__ __forceinline__ void stage_tiles(
    uint32_t sb,
    const bf16* __restrict__ Ah, const bf16* __restrict__ Al, int lda,
    const bf16* __restrict__ Bh, const bf16* __restrict__ Bl, int ldb,
    int row0, int col0, int k0, int ntB, int tid)
{
#pragma unroll
    for (int j = 0; j < 2; j++) {
        const int id = tid + j * 256;
        const int m = id >> 2, c = id & 3;
        const int m6 = m & 63, side = m >> 6;
        const int cc = ((side << 2) | c) ^ (m6 & 7);
        const uint32_t off = (uint32_t)(m6 * 128 + cc * 16);
        const size_t gp = (size_t)(row0 + m) * lda + k0 + c * 8;
        cpa16(sb + off, Ah + gp);
        cpa16(sb + 8192 + off, Al + gp);
    }
    if (ntB) {
#pragma unroll
        for (int j = 0; j < 2; j++) {
            const int id = tid + j * 256;
            const int n = id >> 2, c = id & 3;
            const int n6 = n & 63, side = n >> 6;
            const int cc = ((side << 2) | c) ^ (n6 & 7);
            const uint32_t off = (uint32_t)(n6 * 128 + cc * 16);
            const size_t gp = (size_t)(col0 + n) * ldb + k0 + c * 8;
            cpa16(sb + 16384 + off, Bh + gp);
            cpa16(sb + 24576 + off, Bl + gp);
        }
    } else {
#pragma unroll
        for (int j = 0; j < 2; j++) {
            const int id = tid + j * 256;
            const int k = id >> 4, c = id & 15;
            const int sub = c >> 3;
            const int cw = (c & 7) ^ (k & 7);
            const uint32_t off = (uint32_t)(sub * 4096 + k * 128 + cw * 16);
            const size_t gp = (size_t)(k0 + k) * ldb + col0 + c * 8;
            cpa16(sb + 16384 + off, Bh + gp);
            cpa16(sb + 24576 + off, Bl + gp);
        }
    }
}

__global__ void __launch_bounds__(256) tc5_gemm(
    const bf16* __restrict__ Ah, const bf16* __restrict__ Al, int lda, size_t sA,
    const bf16* __restrict__ Bh, const bf16* __restrict__ Bl, int ldb, size_t sB,
    const float* __restrict__ Res, int ldres, size_t sRes,
    float* __restrict__ Cf, bf16* __restrict__ Ch, bf16* __restrict__ Cl,
    int ldc, size_t sC,
    int K, int ntB, int causal, float scale)
{
    if (causal == 1 && blockIdx.x > blockIdx.y) return;

    extern __shared__ char smem[];
    const uint32_t sbase = smem_u32(smem);

    Ah += (size_t)blockIdx.z * sA;
    Al += (size_t)blockIdx.z * sA;
    Bh += (size_t)blockIdx.z * sB;
    Bl += (size_t)blockIdx.z * sB;
    if (Cf) Cf += (size_t)blockIdx.z * sC;
    else    { Ch += (size_t)blockIdx.z * sC; Cl += (size_t)blockIdx.z * sC; }
    if (Res) Res += (size_t)blockIdx.z * sRes;

    const int tid  = threadIdx.x;
    const int lane = tid & 31;
    const int wid  = tid >> 5;
    const int wm   = wid >> 1;
    const int wn   = wid & 1;
    const int row0 = blockIdx.y * 128;
    const int col0 = blockIdx.x * 128;

    const int kEnd = (causal == 2) ? min(K, (int)(blockIdx.y + 1) * 128) : K;
    const int nch  = kEnd >> 5;

    float acc[2][8][4];
#pragma unroll
    for (int m = 0; m < 2; m++)
#pragma unroll
        for (int n = 0; n < 8; n++)
#pragma unroll
            for (int i = 0; i < 4; i++) acc[m][n][i] = 0.f;

    // prologue: stage chunks 0 and 1
    stage_tiles(sbase, Ah, Al, lda, Bh, Bl, ldb, row0, col0, 0, ntB, tid);
    CPA_COMMIT();
    if (nch > 1) {
        stage_tiles(sbase + STG_SZ, Ah, Al, lda, Bh, Bl, ldb,
                    row0, col0, 32, ntB, tid);
        CPA_COMMIT();
    }

    for (int ch = 0; ch < nch; ch++) {
        if (ch + 1 < nch) { CPA_WAIT(1); } else { CPA_WAIT(0); }
        __syncthreads();

        if (ch + 2 < nch) {
            stage_tiles(sbase + ((ch + 2) % 3) * STG_SZ, Ah, Al, lda,
                        Bh, Bl, ldb, row0, col0, (ch + 2) * 32, ntB, tid);
            CPA_COMMIT();
        }

        const uint32_t base = sbase + (ch % 3) * STG_SZ;

#pragma unroll
        for (int kk = 0; kk < 32; kk += 16) {
            unsigned int ah[2][4], al[2][4];
#pragma unroll
            for (int mt = 0; mt < 2; mt++) {
                const int m  = wm * 32 + mt * 16 + (lane & 15);
                const int m6 = m & 63, side = m >> 6;
                const int cc = (side * 4 + (kk >> 3) + (lane >> 4)) ^ (m6 & 7);
                const uint32_t a = base + (uint32_t)(m6 * 128 + cc * 16);
                ldm4u(ah[mt], a);
                ldm4u(al[mt], a + 8192);
            }
#pragma unroll
            for (int g = 0; g < 4; g++) {
                unsigned int bh[2][2], bl[2][2];
                if (ntB) {
                    const int n  = wn * 64 + g * 16 + (lane & 15);
                    const int n6 = n & 63, side = n >> 6;
                    const int cc = (side * 4 + (kk >> 3) + (lane >> 4)) ^ (n6 & 7);
                    const uint32_t a = base + 16384u + (uint32_t)(n6 * 128 + cc * 16);
                    unsigned int r[4];
                    ldm4u(r, a);
                    bh[0][0] = r[0]; bh[0][1] = r[2];
                    bh[1][0] = r[1]; bh[1][1] = r[3];
                    ldm4u(r, a + 8192);
                    bl[0][0] = r[0]; bl[0][1] = r[2];
                    bl[1][0] = r[1]; bl[1][1] = r[3];
                } else {
                    const int kr = kk + (lane & 15);
                    const int c  = wn * 8 + g * 2 + (lane >> 4);
                    const int sub = c >> 3;
                    const int cw  = (c & 7) ^ (kr & 7);
                    const uint32_t a = base + 16384u
                        + (uint32_t)(sub * 4096 + kr * 128 + cw * 16);
                    unsigned int r[4];
                    ldm4tu(r, a);
                    bh[0][0] = r[0]; bh[0][1] = r[1];
                    bh[1][0] = r[2]; bh[1][1] = r[3];
                    ldm4tu(r, a + 8192);
                    bl[0][0] = r[0]; bl[0][1] = r[1];
                    bl[1][0] = r[2]; bl[1][1] = r[3];
                }
#pragma unroll
                for (int jj = 0; jj < 2; jj++) {
                    const int nt = 2 * g + jj;
#pragma unroll
                    for (int mt = 0; mt < 2; mt++) {
                        mma16816(acc[mt][nt], ah[mt], bh[jj]);
                        mma16816(acc[mt][nt], al[mt], bh[jj]);
                        mma16816(acc[mt][nt], ah[mt], bl[jj]);
                    }
                }
            }
        }
    }

    // ---- epilogue ----
#pragma unroll
    for (int mt = 0; mt < 2; mt++) {
        const int r0 = row0 + wm * 32 + mt * 16 + (lane >> 2);
#pragma unroll
        for (int nt = 0; nt < 8; nt++) {
            const int c = col0 + wn * 64 + nt * 8 + (lane & 3) * 2;
            float2 v0 = make_float2(acc[mt][nt][0] * scale, acc[mt][nt][1] * scale);
            float2 v1 = make_float2(acc[mt][nt][2] * scale, acc[mt][nt][3] * scale);
            if (Cf) {
                if (Res) {
                    const float2 q0 = *reinterpret_cast<const float2*>(
                        Res + (size_t)r0 * ldres + c);
                    const float2 q1 = *reinterpret_cast<const float2*>(
                        Res + (size_t)(r0 + 8) * ldres + c);
                    v0.x += q0.x; v0.y += q0.y; v1.x += q1.x; v1.y += q1.y;
                }
                *reinterpret_cast<float2*>(Cf + (size_t)r0 * ldc + c) = v0;
                *reinterpret_cast<float2*>(Cf + (size_t)(r0 + 8) * ldc + c) = v1;
            } else {
                bf16 h0, l0, h1, l1;
                split1(v0.x, &h0, &l0); split1(v0.y, &h1, &l1);
                *reinterpret_cast<bf162*>(Ch + (size_t)r0 * ldc + c) =
                    __halves2bfloat162(h0, h1);
                *reinterpret_cast<bf162*>(Cl + (size_t)r0 * ldc + c) =
                    __halves2bfloat162(l0, l1);
                split1(v1.x, &h0, &l0); split1(v1.y, &h1, &l1);
                *reinterpret_cast<bf162*>(Ch + (size_t)(r0 + 8) * ldc + c) =
                    __halves2bfloat162(h0, h1);
                *reinterpret_cast<bf162*>(Cl + (size_t)(r0 + 8) * ldc + c) =
                    __halves2bfloat162(l0, l1);
            }
        }
    }
}

// ---------------- elementwise kernels --------------------------------------
__global__ __launch_bounds__(256) void split_kernel(
    const float* __restrict__ in, bf16* __restrict__ hi, bf16* __restrict__ lo)
{
    const size_t i4 = (size_t)blockIdx.x * 256 + threadIdx.x;
    const float4 v = reinterpret_cast<const float4*>(in)[i4];
    bf16 h0, l0, h1, l1;
    split1(v.x, &h0, &l0); split1(v.y, &h1, &l1);
    reinterpret_cast<bf162*>(hi)[i4 * 2]     = __halves2bfloat162(h0, h1);
    reinterpret_cast<bf162*>(lo)[i4 * 2]     = __halves2bfloat162(l0, l1);
    split1(v.z, &h0, &l0); split1(v.w, &h1, &l1);
    reinterpret_cast<bf162*>(hi)[i4 * 2 + 1] = __halves2bfloat162(h0, h1);
    reinterpret_cast<bf162*>(lo)[i4 * 2 + 1] = __halves2bfloat162(l0, l1);
}

__global__ __launch_bounds__(256) void rmsnorm_split_kernel(
    const float* __restrict__ x, const float* __restrict__ w,
    bf16* __restrict__ hi, bf16* __restrict__ lo)
{
    const int row = blockIdx.x;
    const float4* xr = reinterpret_cast<const float4*>(x + (size_t)row * D);
    float4 va[2];
    float ss = 0.f;
#pragma unroll
    for (int i = 0; i < 2; i++) {
        va[i] = xr[threadIdx.x + i * 256];
        ss += va[i].x * va[i].x + va[i].y * va[i].y +
              va[i].z * va[i].z + va[i].w * va[i].w;
    }
    __shared__ float red[256];
    red[threadIdx.x] = ss;
    __syncthreads();
    for (int s = 128; s > 0; s >>= 1) {
        if (threadIdx.x < s) red[threadIdx.x] += red[threadIdx.x + s];
        __syncthreads();
    }
    const float r = rsqrtf(red[0] * (1.0f / D) + EPS);
    const float4* w4 = reinterpret_cast<const float4*>(w);
#pragma unroll
    for (int i = 0; i < 2; i++) {
        const float4 wv = w4[threadIdx.x + i * 256];
        const size_t o2 = ((size_t)row * D) / 2 + (threadIdx.x + i * 256) * 2;
        bf16 h0, l0, h1, l1;
        split1(va[i].x * r * wv.x, &h0, &l0);
        split1(va[i].y * r * wv.y, &h1, &l1);
        reinterpret_cast<bf162*>(hi)[o2]     = __halves2bfloat162(h0, h1);
        reinterpret_cast<bf162*>(lo)[o2]     = __halves2bfloat162(l0, l1);
        split1(va[i].z * r * wv.z, &h0, &l0);
        split1(va[i].w * r * wv.w, &h1, &l1);
        reinterpret_cast<bf162*>(hi)[o2 + 1] = __halves2bfloat162(h0, h1);
        reinterpret_cast<bf162*>(lo)[o2 + 1] = __halves2bfloat162(l0, l1);
    }
}

__global__ __launch_bounds__(256) void rope_split_kernel(
    const float* __restrict__ q, const float* __restrict__ k,
    const float* __restrict__ cs, const float* __restrict__ sn,
    bf16* __restrict__ qh, bf16* __restrict__ ql,
    bf16* __restrict__ kh, bf16* __restrict__ kl)
{
    const int idx = blockIdx.x * 256 + threadIdx.x;   // over S*D/2
    const int s   = idx / (D / 2);
    const int rem = idx % (D / 2);
    const int h   = rem >> 6;
    const int d   = rem & 63;
    const size_t p0 = (size_t)s * D + h * HD + d;
    const size_t p1 = p0 + 64;
    const float c0 = cs[s * HD + d],      s0 = sn[s * HD + d];
    const float c1 = cs[s * HD + d + 64], s1 = sn[s * HD + d + 64];

    bf16 hh, ll;
    const float q0 = q[p0], q1 = q[p1];
    split1(q0 * c0 - q1 * s0, &hh, &ll); qh[p0] = hh; ql[p0] = ll;
    split1(q1 * c1 + q0 * s1, &hh, &ll); qh[p1] = hh; ql[p1] = ll;
    const float k0 = k[p0], k1 = k[p1];
    split1(k0 * c0 - k1 * s0, &hh, &ll); kh[p0] = hh; kl[p0] = ll;
    split1(k1 * c1 + k0 * s1, &hh, &ll); kh[p1] = hh; kl[p1] = ll;
}

__global__ __launch_bounds__(256) void softmax_split_kernel(
    const float* __restrict__ sc, bf16* __restrict__ ph, bf16* __restrict__ pl)
{
    const int i = blockIdx.x, h = blockIdx.y;
    const float* row = sc + ((size_t)h * S + i) * S;
    bf16* oh = ph + ((size_t)h * S + i) * S;
    bf16* ol = pl + ((size_t)h * S + i) * S;
    const int n = i + 1;

    float vals[8];
    float mx = -1e30f;
#pragma unroll
    for (int it = 0; it < 8; it++) {
        const int j = threadIdx.x + it * 256;
        vals[it] = (j < n) ? row[j] : -1e30f;
        mx = fmaxf(mx, vals[it]);
    }
    __shared__ float red[256];
    red[threadIdx.x] = mx;
    __syncthreads();
    for (int s = 128; s > 0; s >>= 1) {
        if (threadIdx.x < s)
            red[threadIdx.x] = fmaxf(red[threadIdx.x], red[threadIdx.x + s]);
        __syncthreads();
    }
    mx = red[0];
    __syncthreads();

    float sum = 0.f;
#pragma unroll
    for (int it = 0; it < 8; it++) {
        const int j = threadIdx.x + it * 256;
        vals[it] = (j < n) ? __expf(vals[it] - mx) : 0.f;
        sum += vals[it];
    }
    red[threadIdx.x] = sum;
    __syncthreads();
    for (int s = 128; s > 0; s >>= 1) {
        if (threadIdx.x < s) red[threadIdx.x] += red[threadIdx.x + s];
        __syncthreads();
    }
    const float inv = 1.f / red[0];

#pragma unroll
    for (int it = 0; it < 8; it++) {
        const int j = threadIdx.x + it * 256;
        bf16 hh, ll;
        split1(vals[it] * inv, &hh, &ll);
        oh[j] = hh; ol[j] = ll;
    }
}

__global__ __launch_bounds__(256) void silu_split_kernel(
    const float* __restrict__ h1, const float* __restrict__ h3,
    bf16* __restrict__ gh, bf16* __restrict__ gl)
{
    const size_t i4 = (size_t)blockIdx.x * 256 + threadIdx.x;
    const float4 a = reinterpret_cast<const float4*>(h1)[i4];
    const float4 b = reinterpret_cast<const float4*>(h3)[i4];
    float4 o;
    o.x = a.x / (1.f + __expf(-a.x)) * b.x;
    o.y = a.y / (1.f + __expf(-a.y)) * b.y;
    o.z = a.z / (1.f + __expf(-a.z)) * b.z;
    o.w = a.w / (1.f + __expf(-a.w)) * b.w;
    bf16 h0, l0, h1b, l1;
    split1(o.x, &h0, &l0); split1(o.y, &h1b, &l1);
    reinterpret_cast<bf162*>(gh)[i4 * 2]     = __halves2bfloat162(h0, h1b);
    reinterpret_cast<bf162*>(gl)[i4 * 2]     = __halves2bfloat162(l0, l1);
    split1(o.z, &h0, &l0); split1(o.w, &h1b, &l1);
    reinterpret_cast<bf162*>(gh)[i4 * 2 + 1] = __halves2bfloat162(h0, h1b);
    reinterpret_cast<bf162*>(gl)[i4 * 2 + 1] = __halves2bfloat162(l0, l1);
}

// ---------------- launch ---------------------------------------------------
extern "C" void kernel_launch(void* const* d_in, const int* in_sizes, int n_in,
                              void* d_out, int out_size)
{
    const float* x    = (const float*)d_in[0];
    const float* fcos = (const float*)d_in[2];
    const float* fsin = (const float*)d_in[3];
    const float* wq   = (const float*)d_in[4];
    const float* wk   = (const float*)d_in[5];
    const float* wv   = (const float*)d_in[6];
    const float* wo   = (const float*)d_in[7];
    const float* w1   = (const float*)d_in[8];
    const float* w2   = (const float*)d_in[9];
    const float* w3   = (const float*)d_in[10];
    const float* anw  = (const float*)d_in[11];
    const float* fnw  = (const float*)d_in[12];
    float* out = (float*)d_out;

    float *qf, *kf, *x1, *h1, *h3, *sc;
    bf16 *nxh, *nxl, *qh, *ql, *kh, *kl, *vh, *vl, *ath, *atl;
    bf16 *nx2h, *nx2l, *gh, *gl, *ph, *pl;
    bf16 *wqh, *wql, *wkh, *wkl, *wvh, *wvl, *woh, *wol;
    bf16 *w1h, *w1l, *w3h, *w3l, *w2h, *w2l;

    cudaGetSymbolAddress((void**)&qf,  g_qf);
    cudaGetSymbolAddress((void**)&kf,  g_kf);
    cudaGetSymbolAddress((void**)&x1,  g_x1);
    cudaGetSymbolAddress((void**)&h1,  g_h1);
    cudaGetSymbolAddress((void**)&h3,  g_h3);
    cudaGetSymbolAddress((void**)&sc,  g_sc);
    cudaGetSymbolAddress((void**)&nxh, g_nxh);  cudaGetSymbolAddress((void**)&nxl, g_nxl);
    cudaGetSymbolAddress((void**)&qh,  g_qh);   cudaGetSymbolAddress((void**)&ql,  g_ql);
    cudaGetSymbolAddress((void**)&kh,  g_kh);   cudaGetSymbolAddress((void**)&kl,  g_kl);
    cudaGetSymbolAddress((void**)&vh,  g_vh);   cudaGetSymbolAddress((void**)&vl,  g_vl);
    cudaGetSymbolAddress((void**)&ath, g_ath);  cudaGetSymbolAddress((void**)&atl, g_atl);
    cudaGetSymbolAddress((void**)&nx2h, g_nx2h); cudaGetSymbolAddress((void**)&nx2l, g_nx2l);
    cudaGetSymbolAddress((void**)&gh,  g_gh);   cudaGetSymbolAddress((void**)&gl,  g_gl);
    cudaGetSymbolAddress((void**)&ph,  g_ph);   cudaGetSymbolAddress((void**)&pl,  g_pl);
    cudaGetSymbolAddress((void**)&wqh, g_wqh);  cudaGetSymbolAddress((void**)&wql, g_wql);
    cudaGetSymbolAddress((void**)&wkh, g_wkh);  cudaGetSymbolAddress((void**)&wkl, g_wkl);
    cudaGetSymbolAddress((void**)&wvh, g_wvh);  cudaGetSymbolAddress((void**)&wvl, g_wvl);
    cudaGetSymbolAddress((void**)&woh, g_woh);  cudaGetSymbolAddress((void**)&wol, g_wol);
    cudaGetSymbolAddress((void**)&w1h, g_w1h);  cudaGetSymbolAddress((void**)&w1l, g_w1l);
    cudaGetSymbolAddress((void**)&w3h, g_w3h);  cudaGetSymbolAddress((void**)&w3l, g_w3l);
    cudaGetSymbolAddress((void**)&w2h, g_w2h);  cudaGetSymbolAddress((void**)&w2l, g_w2l);

    cudaFuncSetAttribute(tc5_gemm,
        cudaFuncAttributeMaxDynamicSharedMemorySize, SMEM_SZ);

    const dim3 gProj(D / 128, S / 128);
    const dim3 gFfn (II / 128, S / 128);
    const dim3 gSc  (S / 128, S / 128, H);
    const dim3 gPv  (HD / 128, S / 128, H);
    const float iscale = 0.08838834764831845f; // 1/sqrt(128)

    const int nDD = (D * D) / 1024;      // float4s / 256
    const int nDI = (D * II) / 1024;

    // weight splits
    split_kernel<<<nDD, 256>>>(wq, wqh, wql);
    split_kernel<<<nDD, 256>>>(wk, wkh, wkl);
    split_kernel<<<nDD, 256>>>(wv, wvh, wvl);
    split_kernel<<<nDD, 256>>>(wo, woh, wol);
    split_kernel<<<nDI, 256>>>(w1, w1h, w1l);
    split_kernel<<<nDI, 256>>>(w3, w3h, w3l);
    split_kernel<<<nDI, 256>>>(w2, w2h, w2l);

    rmsnorm_split_kernel<<<S, 256>>>(x, anw, nxh, nxl);

    // q, k -> fp32 (rope consumes); v -> split directly
    tc5_gemm<<<gProj, 256, SMEM_SZ>>>(nxh, nxl, D, 0, wqh, wql, D, 0,
        nullptr, 0, 0, qf, nullptr, nullptr, D, 0, D, 0, 0, 1.f);
    tc5_gemm<<<gProj, 256, SMEM_SZ>>>(nxh, nxl, D, 0, wkh, wkl, D, 0,
        nullptr, 0, 0, kf, nullptr, nullptr, D, 0, D, 0, 0, 1.f);
    tc5_gemm<<<gProj, 256, SMEM_SZ>>>(nxh, nxl, D, 0, wvh, wvl, D, 0,
        nullptr, 0, 0, nullptr, vh, vl, D, 0, D, 0, 0, 1.f);

    rope_split_kernel<<<(S * D / 2) / 256, 256>>>(qf, kf, fcos, fsin,
                                                  qh, ql, kh, kl);

    // scores = q k^T / sqrt(hd): NT, causal block skip
    tc5_gemm<<<gSc, 256, SMEM_SZ>>>(qh, ql, D, HD, kh, kl, D, HD,
        nullptr, 0, 0, sc, nullptr, nullptr, S, (size_t)S * S,
        HD, 1, 1, iscale);

    softmax_split_kernel<<<dim3(S, H), 256>>>(sc, ph, pl);

    // att = P @ V: NN, causal K-limit; split out
    tc5_gemm<<<gPv, 256, SMEM_SZ>>>(ph, pl, S, (size_t)S * S, vh, vl, D, HD,
        nullptr, 0, 0, nullptr, ath, atl, D, HD, S, 0, 2, 1.f);

    // out proj + residual
    tc5_gemm<<<gProj, 256, SMEM_SZ>>>(ath, atl, D, 0, woh, wol, D, 0,
        x, D, 0, x1, nullptr, nullptr, D, 0, D, 0, 0, 1.f);

    rmsnorm_split_kernel<<<S, 256>>>(x1, fnw, nx2h, nx2l);

    tc5_gemm<<<gFfn, 256, SMEM_SZ>>>(nx2h, nx2l, D, 0, w1h, w1l, II, 0,
        nullptr, 0, 0, h1, nullptr, nullptr, II, 0, D, 0, 0, 1.f);
    tc5_gemm<<<gFfn, 256, SMEM_SZ>>>(nx2h, nx2l, D, 0, w3h, w3l, II, 0,
        nullptr, 0, 0, h3, nullptr, nullptr, II, 0, D, 0, 0, 1.f);

    silu_split_kernel<<<(S * (size_t)II / 4) / 256, 256>>>(h1, h3, gh, gl);

    // down proj + residual -> output
    tc5_gemm<<<gProj, 256, SMEM_SZ>>>(gh, gl, II, 0, w2h, w2l, D, 0,
        x1, D, 0, out, nullptr, nullptr, D, 0, II, 0, 0, 1.f);
}

// round 6
// speedup vs baseline: 2.7821x; 1.1011x over previous
#include <cuda_runtime.h>
#include <cuda_bf16.h>
#include <stdint.h>
#include <math.h>

#define S 2048
#define D 2048
#define H 16
#define HD 128
#define II 8192
#define EPS 1e-5f

typedef __nv_bfloat16 bf16;
typedef __nv_bfloat162 bf162;

// ---------------- scratch (static device globals; no allocation) ----------
__device__ float g_qkvf[(size_t)S * 3 * D];
__device__ float g_x1  [(size_t)S * D];
__device__ float g_h13 [(size_t)S * 2 * II];
__device__ bf16 g_nxh [(size_t)S * D],  g_nxl [(size_t)S * D];
__device__ bf16 g_qh  [(size_t)S * D],  g_ql  [(size_t)S * D];
__device__ bf16 g_kh  [(size_t)S * D],  g_kl  [(size_t)S * D];
__device__ bf16 g_vh  [(size_t)S * D],  g_vl  [(size_t)S * D];
__device__ bf16 g_ath [(size_t)S * D],  g_atl [(size_t)S * D];
__device__ bf16 g_nx2h[(size_t)S * D],  g_nx2l[(size_t)S * D];
__device__ bf16 g_gh  [(size_t)S * II], g_gl  [(size_t)S * II];
__device__ bf16 g_wqkvh[(size_t)D * 3 * D], g_wqkvl[(size_t)D * 3 * D];
__device__ bf16 g_woh [(size_t)D * D],  g_wol [(size_t)D * D];
__device__ bf16 g_w13h[(size_t)D * 2 * II], g_w13l[(size_t)D * 2 * II];
__device__ bf16 g_w2h [(size_t)II * D], g_w2l [(size_t)II * D];

// ---------------- PTX helpers ---------------------------------------------
__device__ __forceinline__ uint32_t smem_u32(const void* p)
{
    uint32_t a;
    asm("{ .reg .u64 t; cvta.to.shared.u64 t, %1; cvt.u32.u64 %0, t; }"
        : "=r"(a) : "l"(p));
    return a;
}

__device__ __forceinline__ void cpa16(uint32_t dst, const void* src)
{
    asm volatile("cp.async.cg.shared.global [%0], [%1], 16;"
                 :: "r"(dst), "l"(src));
}
#define CPA_COMMIT() asm volatile("cp.async.commit_group;" ::: "memory")
#define CPA_WAIT(n)  asm volatile("cp.async.wait_group %0;" :: "n"(n) : "memory")

__device__ __forceinline__ void ldm4u(unsigned int* r, uint32_t a)
{
    asm volatile("ldmatrix.sync.aligned.m8n8.x4.shared.b16 {%0,%1,%2,%3},[%4];"
                 : "=r"(r[0]), "=r"(r[1]), "=r"(r[2]), "=r"(r[3]) : "r"(a));
}
__device__ __forceinline__ void ldm4tu(unsigned int* r, uint32_t a)
{
    asm volatile("ldmatrix.sync.aligned.m8n8.x4.trans.shared.b16 {%0,%1,%2,%3},[%4];"
                 : "=r"(r[0]), "=r"(r[1]), "=r"(r[2]), "=r"(r[3]) : "r"(a));
}
__device__ __forceinline__ void mma16816(float* d, const unsigned int* a,
                                         const unsigned int* b)
{
    asm volatile(
        "mma.sync.aligned.m16n8k16.row.col.f32.bf16.bf16.f32 "
        "{%0,%1,%2,%3},{%4,%5,%6,%7},{%8,%9},{%0,%1,%2,%3};"
        : "+f"(d[0]), "+f"(d[1]), "+f"(d[2]), "+f"(d[3])
        : "r"(a[0]), "r"(a[1]), "r"(a[2]), "r"(a[3]), "r"(b[0]), "r"(b[1]));
}

__device__ __forceinline__ void split1(float x, bf16* h, bf16* l)
{
    bf16 hh = __float2bfloat16_rn(x);
    *h = hh;
    *l = __float2bfloat16_rn(x - __bfloat162float(hh));
}

__device__ __forceinline__ unsigned pack_hilo(float a, float b, unsigned* lo)
{
    bf16 ha, la, hb, lb;
    split1(a, &ha, &la);
    split1(b, &hb, &lb);
    bf162 th = __halves2bfloat162(ha, hb);
    bf162 tl = __halves2bfloat162(la, lb);
    *lo = *reinterpret_cast<unsigned*>(&tl);
    return *reinterpret_cast<unsigned*>(&th);
}

// ---------------- bf16x3 GEMM on mma.sync, cp.async 3-stage pipeline ------
#define STG_SZ 32768
#define SMEM_SZ (3 * STG_SZ)

__device__ __forceinline__ void stage_tiles(
    uint32_t sb,
    const bf16* __restrict__ Ah, const bf16* __restrict__ Al, int lda,
    const bf16* __restrict__ Bh, const bf16* __restrict__ Bl, int ldb,
    int row0, int col0, int k0, int ntB, int tid)
{
#pragma unroll
    for (int j = 0; j < 2; j++) {
        const int id = tid + j * 256;
        const int m = id >> 2, c = id & 3;
        const int m6 = m & 63, side = m >> 6;
        const int cc = ((side << 2) | c) ^ (m6 & 7);
        const uint32_t off = (uint32_t)(m6 * 128 + cc * 16);
        const size_t gp = (size_t)(row0 + m) * lda + k0 + c * 8;
        cpa16(sb + off, Ah + gp);
        cpa16(sb + 8192 + off, Al + gp);
    }
    if (ntB) {
#pragma unroll
        for (int j = 0; j < 2; j++) {
            const int id = tid + j * 256;
            const int n = id >> 2, c = id & 3;
            const int n6 = n & 63, side = n >> 6;
            const int cc = ((side << 2) | c) ^ (n6 & 7);
            const uint32_t off = (uint32_t)(n6 * 128 + cc * 16);
            const size_t gp = (size_t)(col0 + n) * ldb + k0 + c * 8;
            cpa16(sb + 16384 + off, Bh + gp);
            cpa16(sb + 24576 + off, Bl + gp);
        }
    } else {
#pragma unroll
        for (int j = 0; j < 2; j++) {
            const int id = tid + j * 256;
            const int k = id >> 4, c = id & 15;
            const int sub = c >> 3;
            const int cw = (c & 7) ^ (k & 7);
            const uint32_t off = (uint32_t)(sub * 4096 + k * 128 + cw * 16);
            const size_t gp = (size_t)(k0 + k) * ldb + col0 + c * 8;
            cpa16(sb + 16384 + off, Bh + gp);
            cpa16(sb + 24576 + off, Bl + gp);
        }
    }
}

__global__ void __launch_bounds__(256) tc5_gemm(
    const bf16* __restrict__ Ah, const bf16* __restrict__ Al, int lda, size_t sA,
    const bf16* __restrict__ Bh, const bf16* __restrict__ Bl, int ldb, size_t sB,
    const float* __restrict__ Res, int ldres, size_t sRes,
    float* __restrict__ Cf, bf16* __restrict__ Ch, bf16* __restrict__ Cl,
    int ldc, size_t sC,
    int K, int ntB, float scale)
{
    extern __shared__ char smem[];
    const uint32_t sbase = smem_u32(smem);

    Ah += (size_t)blockIdx.z * sA;
    Al += (size_t)blockIdx.z * sA;
    Bh += (size_t)blockIdx.z * sB;
    Bl += (size_t)blockIdx.z * sB;
    if (Cf) Cf += (size_t)blockIdx.z * sC;
    else    { Ch += (size_t)blockIdx.z * sC; Cl += (size_t)blockIdx.z * sC; }
    if (Res) Res += (size_t)blockIdx.z * sRes;

    const int tid  = threadIdx.x;
    const int lane = tid & 31;
    const int wid  = tid >> 5;
    const int wm   = wid >> 1;
    const int wn   = wid & 1;
    const int row0 = blockIdx.y * 128;
    const int col0 = blockIdx.x * 128;

    const int nch = K >> 5;

    float acc[2][8][4];
#pragma unroll
    for (int m = 0; m < 2; m++)
#pragma unroll
        for (int n = 0; n < 8; n++)
#pragma unroll
            for (int i = 0; i < 4; i++) acc[m][n][i] = 0.f;

    stage_tiles(sbase, Ah, Al, lda, Bh, Bl, ldb, row0, col0, 0, ntB, tid);
    CPA_COMMIT();
    if (nch > 1) {
        stage_tiles(sbase + STG_SZ, Ah, Al, lda, Bh, Bl, ldb,
                    row0, col0, 32, ntB, tid);
        CPA_COMMIT();
    }

    for (int ch = 0; ch < nch; ch++) {
        if (ch + 1 < nch) { CPA_WAIT(1); } else { CPA_WAIT(0); }
        __syncthreads();

        if (ch + 2 < nch) {
            stage_tiles(sbase + ((ch + 2) % 3) * STG_SZ, Ah, Al, lda,
                        Bh, Bl, ldb, row0, col0, (ch + 2) * 32, ntB, tid);
            CPA_COMMIT();
        }

        const uint32_t base = sbase + (ch % 3) * STG_SZ;

#pragma unroll
        for (int kk = 0; kk < 32; kk += 16) {
            unsigned int ah[2][4], al[2][4];
#pragma unroll
            for (int mt = 0; mt < 2; mt++) {
                const int m  = wm * 32 + mt * 16 + (lane & 15);
                const int m6 = m & 63, side = m >> 6;
                const int cc = (side * 4 + (kk >> 3) + (lane >> 4)) ^ (m6 & 7);
                const uint32_t a = base + (uint32_t)(m6 * 128 + cc * 16);
                ldm4u(ah[mt], a);
                ldm4u(al[mt], a + 8192);
            }
#pragma unroll
            for (int g = 0; g < 4; g++) {
                unsigned int bh[2][2], bl[2][2];
                if (ntB) {
                    const int n  = wn * 64 + g * 16 + (lane & 15);
                    const int n6 = n & 63, side = n >> 6;
                    const int cc = (side * 4 + (kk >> 3) + (lane >> 4)) ^ (n6 & 7);
                    const uint32_t a = base + 16384u + (uint32_t)(n6 * 128 + cc * 16);
                    unsigned int r[4];
                    ldm4u(r, a);
                    bh[0][0] = r[0]; bh[0][1] = r[2];
                    bh[1][0] = r[1]; bh[1][1] = r[3];
                    ldm4u(r, a + 8192);
                    bl[0][0] = r[0]; bl[0][1] = r[2];
                    bl[1][0] = r[1]; bl[1][1] = r[3];
                } else {
                    const int kr = kk + (lane & 15);
                    const int c  = wn * 8 + g * 2 + (lane >> 4);
                    const int sub = c >> 3;
                    const int cw  = (c & 7) ^ (kr & 7);
                    const uint32_t a = base + 16384u
                        + (uint32_t)(sub * 4096 + kr * 128 + cw * 16);
                    unsigned int r[4];
                    ldm4tu(r, a);
                    bh[0][0] = r[0]; bh[0][1] = r[1];
                    bh[1][0] = r[2]; bh[1][1] = r[3];
                    ldm4tu(r, a + 8192);
                    bl[0][0] = r[0]; bl[0][1] = r[1];
                    bl[1][0] = r[2]; bl[1][1] = r[3];
                }
#pragma unroll
                for (int jj = 0; jj < 2; jj++) {
                    const int nt = 2 * g + jj;
#pragma unroll
                    for (int mt = 0; mt < 2; mt++) {
                        mma16816(acc[mt][nt], ah[mt], bh[jj]);
                        mma16816(acc[mt][nt], al[mt], bh[jj]);
                        mma16816(acc[mt][nt], ah[mt], bl[jj]);
                    }
                }
            }
        }
    }

#pragma unroll
    for (int mt = 0; mt < 2; mt++) {
        const int r0 = row0 + wm * 32 + mt * 16 + (lane >> 2);
#pragma unroll
        for (int nt = 0; nt < 8; nt++) {
            const int c = col0 + wn * 64 + nt * 8 + (lane & 3) * 2;
            float2 v0 = make_float2(acc[mt][nt][0] * scale, acc[mt][nt][1] * scale);
            float2 v1 = make_float2(acc[mt][nt][2] * scale, acc[mt][nt][3] * scale);
            if (Cf) {
                if (Res) {
                    const float2 q0 = *reinterpret_cast<const float2*>(
                        Res + (size_t)r0 * ldres + c);
                    const float2 q1 = *reinterpret_cast<const float2*>(
                        Res + (size_t)(r0 + 8) * ldres + c);
                    v0.x += q0.x; v0.y += q0.y; v1.x += q1.x; v1.y += q1.y;
                }
                *reinterpret_cast<float2*>(Cf + (size_t)r0 * ldc + c) = v0;
                *reinterpret_cast<float2*>(Cf + (size_t)(r0 + 8) * ldc + c) = v1;
            } else {
                unsigned lo, hi;
                hi = pack_hilo(v0.x, v0.y, &lo);
                *reinterpret_cast<unsigned*>(Ch + (size_t)r0 * ldc + c) = hi;
                *reinterpret_cast<unsigned*>(Cl + (size_t)r0 * ldc + c) = lo;
                hi = pack_hilo(v1.x, v1.y, &lo);
                *reinterpret_cast<unsigned*>(Ch + (size_t)(r0 + 8) * ldc + c) = hi;
                *reinterpret_cast<unsigned*>(Cl + (size_t)(r0 + 8) * ldc + c) = lo;
            }
        }
    }
}

// ---------------- flash attention ------------------------------------------
// One CTA = (q-block of 128 rows, head). 8 warps, warp owns 16 q-rows.
// smem: Qh[32K]@0, Ql[32K]@32768, stage b at 65536+b*65536:
//   Kh+0, Kl+16384, Vh+32768, Vl+49152.  Total 192KB.
#define FSMEM (65536 + 2 * 65536)

__device__ __forceinline__ void fa_stage_kv(
    uint32_t dst, const bf16* __restrict__ kh, const bf16* __restrict__ kl,
    const bf16* __restrict__ vh, const bf16* __restrict__ vl,
    int krow0, int hd0, int tid)
{
#pragma unroll
    for (int j = 0; j < 4; j++) {
        const int id = tid + j * 256;
        const int r = id >> 4, c = id & 15;
        const uint32_t off = (uint32_t)(r * 256 + ((c ^ (r & 7)) * 16));
        const size_t g = (size_t)(krow0 + r) * D + hd0 + c * 8;
        cpa16(dst + off, kh + g);
        cpa16(dst + 16384 + off, kl + g);
        cpa16(dst + 32768 + off, vh + g);
        cpa16(dst + 49152 + off, vl + g);
    }
}

__global__ void __launch_bounds__(256, 1) flash_attn(
    const bf16* __restrict__ qh, const bf16* __restrict__ ql,
    const bf16* __restrict__ kh, const bf16* __restrict__ kl,
    const bf16* __restrict__ vh, const bf16* __restrict__ vl,
    bf16* __restrict__ ath, bf16* __restrict__ atl)
{
    extern __shared__ char smem[];
    const uint32_t sb = smem_u32(smem);
    const int qb  = gridDim.x - 1 - blockIdx.x;   // heavy blocks first
    const int hd0 = blockIdx.y * HD;
    const int q0  = qb * 128;
    const int tid = threadIdx.x, lane = tid & 31, w = tid >> 5;
    const float iscale = 0.08838834764831845f;    // 1/sqrt(128)

    // stage Q (hi/lo) + KV tile 0 in one commit group
#pragma unroll
    for (int j = 0; j < 8; j++) {
        const int id = tid + j * 256;
        const int r = id >> 4, c = id & 15;
        const uint32_t off = (uint32_t)(r * 256 + ((c ^ (r & 7)) * 16));
        const size_t g = (size_t)(q0 + r) * D + hd0 + c * 8;
        cpa16(sb + off, qh + g);
        cpa16(sb + 32768 + off, ql + g);
    }
    fa_stage_kv(sb + 65536, kh, kl, vh, vl, 0, hd0, tid);
    CPA_COMMIT();

    const int nkt = 2 * (qb + 1);

    float m0 = -1e30f, m1 = -1e30f, l0 = 0.f, l1 = 0.f;
    float o[16][4];
#pragma unroll
    for (int nt = 0; nt < 16; nt++)
#pragma unroll
        for (int i = 0; i < 4; i++) o[nt][i] = 0.f;

    const int rloc = w * 16 + (lane & 15);    // q row within block for frags
    const int rowg = q0 + w * 16 + (lane >> 2);

    for (int j = 0; j < nkt; j++) {
        __syncthreads();   // prior reads of buffer (j+1)&1 complete
        if (j + 1 < nkt) {
            fa_stage_kv(sb + 65536u + ((j + 1) & 1) * 65536u,
                        kh, kl, vh, vl, (j + 1) * 64, hd0, tid);
            CPA_COMMIT();
            CPA_WAIT(1);
        } else {
            CPA_WAIT(0);
        }
        __syncthreads();

        const uint32_t kb = sb + 65536u + (j & 1) * 65536u;

        // ---- S = Q K^T (bf16x3), warp computes 16x64 ----
        float s[8][4];
#pragma unroll
        for (int nt = 0; nt < 8; nt++)
#pragma unroll
            for (int i = 0; i < 4; i++) s[nt][i] = 0.f;

#pragma unroll
        for (int ks = 0; ks < 8; ks++) {
            unsigned int aqh[4], aql[4];
            const int cq = (2 * ks + (lane >> 4)) ^ (rloc & 7);
            const uint32_t qa = sb + (uint32_t)(rloc * 256 + cq * 16);
            ldm4u(aqh, qa);
            ldm4u(aql, qa + 32768);
#pragma unroll
            for (int ng = 0; ng < 4; ng++) {
                const int rn = ng * 16 + (lane & 15);
                const int cn = (2 * ks + (lane >> 4)) ^ (rn & 7);
                const uint32_t ka = kb + (uint32_t)(rn * 256 + cn * 16);
                unsigned int r[4], bh[2][2], bl[2][2];
                ldm4u(r, ka);
                bh[0][0] = r[0]; bh[0][1] = r[2];
                bh[1][0] = r[1]; bh[1][1] = r[3];
                ldm4u(r, ka + 16384);
                bl[0][0] = r[0]; bl[0][1] = r[2];
                bl[1][0] = r[1]; bl[1][1] = r[3];
#pragma unroll
                for (int jj = 0; jj < 2; jj++) {
                    const int nt = 2 * ng + jj;
                    mma16816(s[nt], aqh, bh[jj]);
                    mma16816(s[nt], aql, bh[jj]);
                    mma16816(s[nt], aqh, bl[jj]);
                }
            }
        }

        // ---- scale + causal mask + online softmax ----
        float mx0 = -1e30f, mx1 = -1e30f;
#pragma unroll
        for (int nt = 0; nt < 8; nt++) {
            const int col = j * 64 + nt * 8 + (lane & 3) * 2;
            s[nt][0] = (col     <= rowg)     ? s[nt][0] * iscale : -1e30f;
            s[nt][1] = (col + 1 <= rowg)     ? s[nt][1] * iscale : -1e30f;
            s[nt][2] = (col     <= rowg + 8) ? s[nt][2] * iscale : -1e30f;
            s[nt][3] = (col + 1 <= rowg + 8) ? s[nt][3] * iscale : -1e30f;
            mx0 = fmaxf(mx0, fmaxf(s[nt][0], s[nt][1]));
            mx1 = fmaxf(mx1, fmaxf(s[nt][2], s[nt][3]));
        }
        mx0 = fmaxf(mx0, __shfl_xor_sync(0xffffffffu, mx0, 1));
        mx0 = fmaxf(mx0, __shfl_xor_sync(0xffffffffu, mx0, 2));
        mx1 = fmaxf(mx1, __shfl_xor_sync(0xffffffffu, mx1, 1));
        mx1 = fmaxf(mx1, __shfl_xor_sync(0xffffffffu, mx1, 2));
        const float nm0 = fmaxf(m0, mx0);
        const float nm1 = fmaxf(m1, mx1);
        const float al0 = __expf(m0 - nm0);
        const float al1 = __expf(m1 - nm1);
        m0 = nm0; m1 = nm1;

        float sum0 = 0.f, sum1 = 0.f;
#pragma unroll
        for (int nt = 0; nt < 8; nt++) {
            s[nt][0] = __expf(s[nt][0] - nm0);
            s[nt][1] = __expf(s[nt][1] - nm0);
            s[nt][2] = __expf(s[nt][2] - nm1);
            s[nt][3] = __expf(s[nt][3] - nm1);
            sum0 += s[nt][0] + s[nt][1];
            sum1 += s[nt][2] + s[nt][3];
        }
        sum0 += __shfl_xor_sync(0xffffffffu, sum0, 1);
        sum0 += __shfl_xor_sync(0xffffffffu, sum0, 2);
        sum1 += __shfl_xor_sync(0xffffffffu, sum1, 1);
        sum1 += __shfl_xor_sync(0xffffffffu, sum1, 2);
        l0 = l0 * al0 + sum0;
        l1 = l1 * al1 + sum1;

#pragma unroll
        for (int nt = 0; nt < 16; nt++) {
            o[nt][0] *= al0; o[nt][1] *= al0;
            o[nt][2] *= al1; o[nt][3] *= al1;
        }

        // ---- PV: P(hi/lo from s regs) @ V (hi/lo) ----
#pragma unroll
        for (int ks = 0; ks < 4; ks++) {
            unsigned int ph[4], pl[4];
            ph[0] = pack_hilo(s[2 * ks][0],     s[2 * ks][1],     &pl[0]);
            ph[1] = pack_hilo(s[2 * ks][2],     s[2 * ks][3],     &pl[1]);
            ph[2] = pack_hilo(s[2 * ks + 1][0], s[2 * ks + 1][1], &pl[2]);
            ph[3] = pack_hilo(s[2 * ks + 1][2], s[2 * ks + 1][3], &pl[3]);
#pragma unroll
            for (int ng = 0; ng < 8; ng++) {
                const int kr = ks * 16 + (lane & 15);
                const int cv = (ng * 2 + (lane >> 4)) ^ (kr & 7);
                const uint32_t va = kb + 32768u + (uint32_t)(kr * 256 + cv * 16);
                unsigned int r[4], bvh[2][2], bvl[2][2];
                ldm4tu(r, va);
                bvh[0][0] = r[0]; bvh[0][1] = r[1];
                bvh[1][0] = r[2]; bvh[1][1] = r[3];
                ldm4tu(r, va + 16384);
                bvl[0][0] = r[0]; bvl[0][1] = r[1];
                bvl[1][0] = r[2]; bvl[1][1] = r[3];
#pragma unroll
                for (int jj = 0; jj < 2; jj++) {
                    const int nt = 2 * ng + jj;
                    mma16816(o[nt], ph, bvh[jj]);
                    mma16816(o[nt], pl, bvh[jj]);
                    mma16816(o[nt], ph, bvl[jj]);
                }
            }
        }
    }

    // ---- finalize: O / l, split hi/lo, write ----
    const float inv0 = 1.f / l0;
    const float inv1 = 1.f / l1;
#pragma unroll
    for (int nt = 0; nt < 16; nt++) {
        const int c = hd0 + nt * 8 + (lane & 3) * 2;
        unsigned lo, hi;
        hi = pack_hilo(o[nt][0] * inv0, o[nt][1] * inv0, &lo);
        *reinterpret_cast<unsigned*>(ath + (size_t)rowg * D + c) = hi;
        *reinterpret_cast<unsigned*>(atl + (size_t)rowg * D + c) = lo;
        hi = pack_hilo(o[nt][2] * inv1, o[nt][3] * inv1, &lo);
        *reinterpret_cast<unsigned*>(ath + (size_t)(rowg + 8) * D + c) = hi;
        *reinterpret_cast<unsigned*>(atl + (size_t)(rowg + 8) * D + c) = lo;
    }
}

// ---------------- elementwise kernels --------------------------------------
__global__ __launch_bounds__(256) void split_pack_kernel(
    const float* __restrict__ in, bf16* __restrict__ hi, bf16* __restrict__ lo,
    int nsrc, int ndst, int coff)
{
    const size_t i4 = (size_t)blockIdx.x * 256 + threadIdx.x;
    const size_t e  = i4 * 4;
    const size_t row = e / nsrc;
    const size_t col = e % nsrc;
    const float4 v = reinterpret_cast<const float4*>(in)[i4];
    const size_t o2 = (row * ndst + coff + col) / 2;
    unsigned l, h;
    h = pack_hilo(v.x, v.y, &l);
    reinterpret_cast<unsigned*>(hi)[o2]     = h;
    reinterpret_cast<unsigned*>(lo)[o2]     = l;
    h = pack_hilo(v.z, v.w, &l);
    reinterpret_cast<unsigned*>(hi)[o2 + 1] = h;
    reinterpret_cast<unsigned*>(lo)[o2 + 1] = l;
}

__global__ __launch_bounds__(256) void rmsnorm_split_kernel(
    const float* __restrict__ x, const float* __restrict__ w,
    bf16* __restrict__ hi, bf16* __restrict__ lo)
{
    const int row = blockIdx.x;
    const float4* xr = reinterpret_cast<const float4*>(x + (size_t)row * D);
    float4 va[2];
    float ss = 0.f;
#pragma unroll
    for (int i = 0; i < 2; i++) {
        va[i] = xr[threadIdx.x + i * 256];
        ss += va[i].x * va[i].x + va[i].y * va[i].y +
              va[i].z * va[i].z + va[i].w * va[i].w;
    }
    __shared__ float red[256];
    red[threadIdx.x] = ss;
    __syncthreads();
    for (int s = 128; s > 0; s >>= 1) {
        if (threadIdx.x < s) red[threadIdx.x] += red[threadIdx.x + s];
        __syncthreads();
    }
    const float r = rsqrtf(red[0] * (1.0f / D) + EPS);
    const float4* w4 = reinterpret_cast<const float4*>(w);
#pragma unroll
    for (int i = 0; i < 2; i++) {
        const float4 wv = w4[threadIdx.x + i * 256];
        const size_t o2 = ((size_t)row * D) / 2 + (threadIdx.x + i * 256) * 2;
        unsigned l, h;
        h = pack_hilo(va[i].x * r * wv.x, va[i].y * r * wv.y, &l);
        reinterpret_cast<unsigned*>(hi)[o2]     = h;
        reinterpret_cast<unsigned*>(lo)[o2]     = l;
        h = pack_hilo(va[i].z * r * wv.z, va[i].w * r * wv.w, &l);
        reinterpret_cast<unsigned*>(hi)[o2 + 1] = h;
        reinterpret_cast<unsigned*>(lo)[o2 + 1] = l;
    }
}

// rope+split for q,k; plain split for v — from packed qkv fp32 [S, 3D]
__global__ __launch_bounds__(256) void qkv_post_kernel(
    const float* __restrict__ qkv,
    const float* __restrict__ cs, const float* __restrict__ sn,
    bf16* __restrict__ qh, bf16* __restrict__ ql,
    bf16* __restrict__ kh, bf16* __restrict__ kl,
    bf16* __restrict__ vh, bf16* __restrict__ vl)
{
    const int idx = blockIdx.x * 256 + threadIdx.x;   // over S*D/2
    const int s   = idx / (D / 2);
    const int rem = idx % (D / 2);
    const int h   = rem >> 6;
    const int d   = rem & 63;
    const size_t pq0 = (size_t)s * (3 * D) + h * HD + d;
    const size_t pq1 = pq0 + 64;
    const size_t po0 = (size_t)s * D + h * HD + d;
    const size_t po1 = po0 + 64;
    const float c0 = cs[s * HD + d],      s0 = sn[s * HD + d];
    const float c1 = cs[s * HD + d + 64], s1 = sn[s * HD + d + 64];

    bf16 hh, ll;
    const float q0 = qkv[pq0], q1 = qkv[pq1];
    split1(q0 * c0 - q1 * s0, &hh, &ll); qh[po0] = hh; ql[po0] = ll;
    split1(q1 * c1 + q0 * s1, &hh, &ll); qh[po1] = hh; ql[po1] = ll;
    const float k0 = qkv[pq0 + D], k1 = qkv[pq1 + D];
    split1(k0 * c0 - k1 * s0, &hh, &ll); kh[po0] = hh; kl[po0] = ll;
    split1(k1 * c1 + k0 * s1, &hh, &ll); kh[po1] = hh; kl[po1] = ll;
    split1(qkv[pq0 + 2 * D], &hh, &ll);  vh[po0] = hh; vl[po0] = ll;
    split1(qkv[pq1 + 2 * D], &hh, &ll);  vh[po1] = hh; vl[po1] = ll;
}

// silu(h13[:, :I]) * h13[:, I:] -> split
__global__ __launch_bounds__(256) void silu_split_kernel(
    const float* __restrict__ h13, bf16* __restrict__ gh, bf16* __restrict__ gl)
{
    const size_t i4  = (size_t)blockIdx.x * 256 + threadIdx.x;  // over S*I/4
    const size_t row = i4 / (II / 4);
    const size_t c4  = (i4 % (II / 4)) * 4;
    const size_t b   = row * (2 * II) + c4;
    const float4 a = *reinterpret_cast<const float4*>(h13 + b);
    const float4 g = *reinterpret_cast<const float4*>(h13 + b + II);
    float4 o;
    o.x = a.x / (1.f + __expf(-a.x)) * g.x;
    o.y = a.y / (1.f + __expf(-a.y)) * g.y;
    o.z = a.z / (1.f + __expf(-a.z)) * g.z;
    o.w = a.w / (1.f + __expf(-a.w)) * g.w;
    const size_t o2 = (row * II + c4) / 2;
    unsigned l, h;
    h = pack_hilo(o.x, o.y, &l);
    reinterpret_cast<unsigned*>(gh)[o2]     = h;
    reinterpret_cast<unsigned*>(gl)[o2]     = l;
    h = pack_hilo(o.z, o.w, &l);
    reinterpret_cast<unsigned*>(gh)[o2 + 1] = h;
    reinterpret_cast<unsigned*>(gl)[o2 + 1] = l;
}

// ---------------- launch ---------------------------------------------------
extern "C" void kernel_launch(void* const* d_in, const int* in_sizes, int n_in,
                              void* d_out, int out_size)
{
    const float* x    = (const float*)d_in[0];
    const float* fcos = (const float*)d_in[2];
    const float* fsin = (const float*)d_in[3];
    const float* wq   = (const float*)d_in[4];
    const float* wk   = (const float*)d_in[5];
    const float* wv   = (const float*)d_in[6];
    const float* wo   = (const float*)d_in[7];
    const float* w1   = (const float*)d_in[8];
    const float* w2   = (const float*)d_in[9];
    const float* w3   = (const float*)d_in[10];
    const float* anw  = (const float*)d_in[11];
    const float* fnw  = (const float*)d_in[12];
    float* out = (float*)d_out;

    float *qkvf, *x1, *h13;
    bf16 *nxh, *nxl, *qh, *ql, *kh, *kl, *vh, *vl, *ath, *atl;
    bf16 *nx2h, *nx2l, *gh, *gl;
    bf16 *wqkvh, *wqkvl, *woh, *wol, *w13h, *w13l, *w2h, *w2l;

    cudaGetSymbolAddress((void**)&qkvf, g_qkvf);
    cudaGetSymbolAddress((void**)&x1,   g_x1);
    cudaGetSymbolAddress((void**)&h13,  g_h13);
    cudaGetSymbolAddress((void**)&nxh,  g_nxh);   cudaGetSymbolAddress((void**)&nxl,  g_nxl);
    cudaGetSymbolAddress((void**)&qh,   g_qh);    cudaGetSymbolAddress((void**)&ql,   g_ql);
    cudaGetSymbolAddress((void**)&kh,   g_kh);    cudaGetSymbolAddress((void**)&kl,   g_kl);
    cudaGetSymbolAddress((void**)&vh,   g_vh);    cudaGetSymbolAddress((void**)&vl,   g_vl);
    cudaGetSymbolAddress((void**)&ath,  g_ath);   cudaGetSymbolAddress((void**)&atl,  g_atl);
    cudaGetSymbolAddress((void**)&nx2h, g_nx2h);  cudaGetSymbolAddress((void**)&nx2l, g_nx2l);
    cudaGetSymbolAddress((void**)&gh,   g_gh);    cudaGetSymbolAddress((void**)&gl,   g_gl);
    cudaGetSymbolAddress((void**)&wqkvh, g_wqkvh); cudaGetSymbolAddress((void**)&wqkvl, g_wqkvl);
    cudaGetSymbolAddress((void**)&woh,  g_woh);   cudaGetSymbolAddress((void**)&wol,  g_wol);
    cudaGetSymbolAddress((void**)&w13h, g_w13h);  cudaGetSymbolAddress((void**)&w13l, g_w13l);
    cudaGetSymbolAddress((void**)&w2h,  g_w2h);   cudaGetSymbolAddress((void**)&w2l,  g_w2l);

    cudaFuncSetAttribute(tc5_gemm,
        cudaFuncAttributeMaxDynamicSharedMemorySize, SMEM_SZ);
    cudaFuncSetAttribute(flash_attn,
        cudaFuncAttributeMaxDynamicSharedMemorySize, FSMEM);

    const dim3 gQkv(3 * D / 128, S / 128);       // 48x16
    const dim3 gProj(D / 128, S / 128);          // 16x16
    const dim3 gW13(2 * II / 128, S / 128);      // 128x16
    const dim3 gFa (S / 128, H);                 // 16x16

    const int nDD = (D * D) / 1024;
    const int nDI = (D * II) / 1024;

    // pack + split weights
    split_pack_kernel<<<nDD, 256>>>(wq, wqkvh, wqkvl, D, 3 * D, 0);
    split_pack_kernel<<<nDD, 256>>>(wk, wqkvh, wqkvl, D, 3 * D, D);
    split_pack_kernel<<<nDD, 256>>>(wv, wqkvh, wqkvl, D, 3 * D, 2 * D);
    split_pack_kernel<<<nDD, 256>>>(wo, woh, wol, D, D, 0);
    split_pack_kernel<<<nDI, 256>>>(w1, w13h, w13l, II, 2 * II, 0);
    split_pack_kernel<<<nDI, 256>>>(w3, w13h, w13l, II, 2 * II, II);
    split_pack_kernel<<<nDI, 256>>>(w2, w2h, w2l, D, D, 0);

    rmsnorm_split_kernel<<<S, 256>>>(x, anw, nxh, nxl);

    // fused qkv projection -> fp32 [S, 3D]
    tc5_gemm<<<gQkv, 256, SMEM_SZ>>>(nxh, nxl, D, 0, wqkvh, wqkvl, 3 * D, 0,
        nullptr, 0, 0, qkvf, nullptr, nullptr, 3 * D, 0, D, 0, 1.f);

    qkv_post_kernel<<<(S * D / 2) / 256, 256>>>(qkvf, fcos, fsin,
                                                qh, ql, kh, kl, vh, vl);

    flash_attn<<<gFa, 256, FSMEM>>>(qh, ql, kh, kl, vh, vl, ath, atl);

    tc5_gemm<<<gProj, 256, SMEM_SZ>>>(ath, atl, D, 0, woh, wol, D, 0,
        x, D, 0, x1, nullptr, nullptr, D, 0, D, 0, 1.f);

    rmsnorm_split_kernel<<<S, 256>>>(x1, fnw, nx2h, nx2l);

    // fused w1/w3 -> fp32 [S, 2I]
    tc5_gemm<<<gW13, 256, SMEM_SZ>>>(nx2h, nx2l, D, 0, w13h, w13l, 2 * II, 0,
        nullptr, 0, 0, h13, nullptr, nullptr, 2 * II, 0, D, 0, 1.f);

    silu_split_kernel<<<(S * (size_t)II / 4) / 256, 256>>>(h13, gh, gl);

    tc5_gemm<<<gProj, 256, SMEM_SZ>>>(gh, gl, II, 0, w2h, w2l, D, 0,
        x1, D, 0, out, nullptr, nullptr, D, 0, II, 0, 1.f);
}

// round 7
// speedup vs baseline: 4.3515x; 1.5641x over previous
#include <cuda_runtime.h>
#include <cuda_fp16.h>
#include <stdint.h>
#include <math.h>

#define S 2048
#define D 2048
#define H 16
#define HD 128
#define II 8192
#define EPS 1e-5f

typedef __half hlf;

// ---------------- scratch (static device globals; no allocation) ----------
__device__ float g_qkvf[(size_t)S * 3 * D];
__device__ float g_x1  [(size_t)S * D];
__device__ float g_h13 [(size_t)S * 2 * II];
__device__ hlf g_nxh [(size_t)S * D],  g_nxl [(size_t)S * D];
__device__ hlf g_qh  [(size_t)S * D],  g_ql  [(size_t)S * D];
__device__ hlf g_kh  [(size_t)S * D];
__device__ hlf g_vh  [(size_t)S * D];
__device__ hlf g_ath [(size_t)S * D],  g_atl [(size_t)S * D];
__device__ hlf g_nx2h[(size_t)S * D],  g_nx2l[(size_t)S * D];
__device__ hlf g_gh  [(size_t)S * II], g_gl  [(size_t)S * II];
__device__ hlf g_wqkvh[(size_t)D * 3 * D];
__device__ hlf g_woh [(size_t)D * D];
__device__ hlf g_w13h[(size_t)D * 2 * II];
__device__ hlf g_w2h [(size_t)II * D];

// ---------------- PTX helpers ---------------------------------------------
__device__ __forceinline__ uint32_t smem_u32(const void* p)
{
    uint32_t a;
    asm("{ .reg .u64 t; cvta.to.shared.u64 t, %1; cvt.u32.u64 %0, t; }"
        : "=r"(a) : "l"(p));
    return a;
}

__device__ __forceinline__ void cpa16(uint32_t dst, const void* src)
{
    asm volatile("cp.async.cg.shared.global [%0], [%1], 16;"
                 :: "r"(dst), "l"(src));
}
#define CPA_COMMIT() asm volatile("cp.async.commit_group;" ::: "memory")
#define CPA_WAIT(n)  asm volatile("cp.async.wait_group %0;" :: "n"(n) : "memory")

__device__ __forceinline__ void ldm4u(unsigned int* r, uint32_t a)
{
    asm volatile("ldmatrix.sync.aligned.m8n8.x4.shared.b16 {%0,%1,%2,%3},[%4];"
                 : "=r"(r[0]), "=r"(r[1]), "=r"(r[2]), "=r"(r[3]) : "r"(a));
}
__device__ __forceinline__ void ldm4tu(unsigned int* r, uint32_t a)
{
    asm volatile("ldmatrix.sync.aligned.m8n8.x4.trans.shared.b16 {%0,%1,%2,%3},[%4];"
                 : "=r"(r[0]), "=r"(r[1]), "=r"(r[2]), "=r"(r[3]) : "r"(a));
}
__device__ __forceinline__ void mma16816(float* d, const unsigned int* a,
                                         const unsigned int* b)
{
    asm volatile(
        "mma.sync.aligned.m16n8k16.row.col.f32.f16.f16.f32 "
        "{%0,%1,%2,%3},{%4,%5,%6,%7},{%8,%9},{%0,%1,%2,%3};"
        : "+f"(d[0]), "+f"(d[1]), "+f"(d[2]), "+f"(d[3])
        : "r"(a[0]), "r"(a[1]), "r"(a[2]), "r"(a[3]), "r"(b[0]), "r"(b[1]));
}

__device__ __forceinline__ void split1h(float x, hlf* h, hlf* l)
{
    hlf hh = __float2half_rn(x);
    *h = hh;
    *l = __float2half_rn(x - __half2float(hh));
}

__device__ __forceinline__ unsigned pack_hilo_h(float a, float b, unsigned* lo)
{
    hlf ha, la, hb, lb;
    split1h(a, &ha, &la);
    split1h(b, &hb, &lb);
    __half2 th = __halves2half2(ha, hb);
    __half2 tl = __halves2half2(la, lb);
    *lo = *reinterpret_cast<unsigned*>(&tl);
    return *reinterpret_cast<unsigned*>(&th);
}

// ---------------- fp16x2 GEMM, cp.async 3-stage pipeline, k64 chunks ------
// C[128,128] = A[M,K](hi+lo) * B[K,N](hi) (+Res). All NN.
// Stage 48KB: Ah 128x64 @0, Al @16384, Bh 64x128 @32768 (two 8K n-halves).
#define STG 49152
#define GSMEM (3 * STG)

__device__ __forceinline__ void stage7(
    uint32_t sb,
    const hlf* __restrict__ Ah, const hlf* __restrict__ Al, int lda,
    const hlf* __restrict__ Bh, int ldb,
    int row0, int col0, int k0, int tid)
{
#pragma unroll
    for (int j = 0; j < 4; j++) {
        const int id = tid + j * 256;
        const int r = id >> 3, c = id & 7;
        const uint32_t off = (uint32_t)(r * 128 + ((c ^ (r & 7)) * 16));
        const size_t g = (size_t)(row0 + r) * lda + k0 + c * 8;
        cpa16(sb + off, Ah + g);
        cpa16(sb + 16384 + off, Al + g);
    }
#pragma unroll
    for (int j = 0; j < 4; j++) {
        const int id = tid + j * 256;
        const int r = id >> 4, c = id & 15;
        const int sub = c >> 3;
        const uint32_t off = (uint32_t)(32768 + sub * 8192 + r * 128
                                        + (((c & 7) ^ (r & 7)) * 16));
        const size_t g = (size_t)(k0 + r) * ldb + col0 + c * 8;
        cpa16(sb + off, Bh + g);
    }
}

__global__ void __launch_bounds__(256) tc7_gemm(
    const hlf* __restrict__ Ah, const hlf* __restrict__ Al, int lda,
    const hlf* __restrict__ Bh, int ldb,
    const float* __restrict__ Res, int ldres,
    float* __restrict__ Cf, int ldc, int K)
{
    extern __shared__ char smem[];
    const uint32_t sbase = smem_u32(smem);

    const int tid  = threadIdx.x;
    const int lane = tid & 31;
    const int wid  = tid >> 5;
    const int wm   = wid >> 1;
    const int wn   = wid & 1;
    const int row0 = blockIdx.y * 128;
    const int col0 = blockIdx.x * 128;

    const int nch = K >> 6;   // K multiple of 64, nch >= 2 for all our shapes

    float acc[2][8][4];
#pragma unroll
    for (int m = 0; m < 2; m++)
#pragma unroll
        for (int n = 0; n < 8; n++)
#pragma unroll
            for (int i = 0; i < 4; i++) acc[m][n][i] = 0.f;

    stage7(sbase, Ah, Al, lda, Bh, ldb, row0, col0, 0, tid);
    CPA_COMMIT();
    stage7(sbase + STG, Ah, Al, lda, Bh, ldb, row0, col0, 64, tid);
    CPA_COMMIT();

    for (int ch = 0; ch < nch; ch++) {
        if (ch + 1 < nch) { CPA_WAIT(1); } else { CPA_WAIT(0); }
        __syncthreads();

        if (ch + 2 < nch) {
            stage7(sbase + ((ch + 2) % 3) * STG, Ah, Al, lda, Bh, ldb,
                   row0, col0, (ch + 2) * 64, tid);
            CPA_COMMIT();
        }

        const uint32_t base = sbase + (ch % 3) * STG;

#pragma unroll
        for (int kk = 0; kk < 64; kk += 16) {
            unsigned int ah[2][4], al[2][4];
#pragma unroll
            for (int mt = 0; mt < 2; mt++) {
                const int m  = wm * 32 + mt * 16 + (lane & 15);
                const int cc = ((kk >> 3) + (lane >> 4)) ^ (m & 7);
                const uint32_t a = base + (uint32_t)(m * 128 + cc * 16);
                ldm4u(ah[mt], a);
                ldm4u(al[mt], a + 16384);
            }
#pragma unroll
            for (int g = 0; g < 4; g++) {
                const int kr = kk + (lane & 15);
                const int c  = wn * 8 + g * 2 + (lane >> 4);
                const int sub = c >> 3;
                const int cw  = (c & 7) ^ (kr & 7);
                const uint32_t a = base + 32768u
                    + (uint32_t)(sub * 8192 + kr * 128 + cw * 16);
                unsigned int r4[4];
                ldm4tu(r4, a);
                unsigned int b0[2] = { r4[0], r4[1] };
                unsigned int b1[2] = { r4[2], r4[3] };
#pragma unroll
                for (int mt = 0; mt < 2; mt++) {
                    mma16816(acc[mt][2 * g],     ah[mt], b0);
                    mma16816(acc[mt][2 * g],     al[mt], b0);
                    mma16816(acc[mt][2 * g + 1], ah[mt], b1);
                    mma16816(acc[mt][2 * g + 1], al[mt], b1);
                }
            }
        }
    }

#pragma unroll
    for (int mt = 0; mt < 2; mt++) {
        const int r0 = row0 + wm * 32 + mt * 16 + (lane >> 2);
#pragma unroll
        for (int nt = 0; nt < 8; nt++) {
            const int c = col0 + wn * 64 + nt * 8 + (lane & 3) * 2;
            float2 v0 = make_float2(acc[mt][nt][0], acc[mt][nt][1]);
            float2 v1 = make_float2(acc[mt][nt][2], acc[mt][nt][3]);
            if (Res) {
                const float2 q0 = *reinterpret_cast<const float2*>(
                    Res + (size_t)r0 * ldres + c);
                const float2 q1 = *reinterpret_cast<const float2*>(
                    Res + (size_t)(r0 + 8) * ldres + c);
                v0.x += q0.x; v0.y += q0.y; v1.x += q1.x; v1.y += q1.y;
            }
            *reinterpret_cast<float2*>(Cf + (size_t)r0 * ldc + c) = v0;
            *reinterpret_cast<float2*>(Cf + (size_t)(r0 + 8) * ldc + c) = v1;
        }
    }
}

// ---------------- flash attention (fp16x2) ----------------------------------
// smem: Qh[32K]@0, Ql[32K]@32768; stage b at 65536+b*32768: Kh+0, Vh+16384.
#define FSMEM (65536 + 2 * 32768)

__device__ __forceinline__ void fa_stage_kv(
    uint32_t dst, const hlf* __restrict__ kh, const hlf* __restrict__ vh,
    int krow0, int hd0, int tid)
{
#pragma unroll
    for (int j = 0; j < 4; j++) {
        const int id = tid + j * 256;
        const int r = id >> 4, c = id & 15;
        const uint32_t off = (uint32_t)(r * 256 + ((c ^ (r & 7)) * 16));
        const size_t g = (size_t)(krow0 + r) * D + hd0 + c * 8;
        cpa16(dst + off, kh + g);
        cpa16(dst + 16384 + off, vh + g);
    }
}

__global__ void __launch_bounds__(256, 1) flash_attn(
    const hlf* __restrict__ qh, const hlf* __restrict__ ql,
    const hlf* __restrict__ kh, const hlf* __restrict__ vh,
    hlf* __restrict__ ath, hlf* __restrict__ atl)
{
    extern __shared__ char smem[];
    const uint32_t sb = smem_u32(smem);
    const int qb  = gridDim.x - 1 - blockIdx.x;   // heavy blocks first
    const int hd0 = blockIdx.y * HD;
    const int q0  = qb * 128;
    const int tid = threadIdx.x, lane = tid & 31, w = tid >> 5;
    const float iscale = 0.08838834764831845f;    // 1/sqrt(128)

#pragma unroll
    for (int j = 0; j < 8; j++) {
        const int id = tid + j * 256;
        const int r = id >> 4, c = id & 15;
        const uint32_t off = (uint32_t)(r * 256 + ((c ^ (r & 7)) * 16));
        const size_t g = (size_t)(q0 + r) * D + hd0 + c * 8;
        cpa16(sb + off, qh + g);
        cpa16(sb + 32768 + off, ql + g);
    }
    fa_stage_kv(sb + 65536, kh, vh, 0, hd0, tid);
    CPA_COMMIT();

    const int nkt = 2 * (qb + 1);

    float m0 = -1e30f, m1 = -1e30f, l0 = 0.f, l1 = 0.f;
    float o[16][4];
#pragma unroll
    for (int nt = 0; nt < 16; nt++)
#pragma unroll
        for (int i = 0; i < 4; i++) o[nt][i] = 0.f;

    const int rloc = w * 16 + (lane & 15);
    const int rowg = q0 + w * 16 + (lane >> 2);

    for (int j = 0; j < nkt; j++) {
        __syncthreads();
        if (j + 1 < nkt) {
            fa_stage_kv(sb + 65536u + ((j + 1) & 1) * 32768u,
                        kh, vh, (j + 1) * 64, hd0, tid);
            CPA_COMMIT();
            CPA_WAIT(1);
        } else {
            CPA_WAIT(0);
        }
        __syncthreads();

        const uint32_t kb = sb + 65536u + (j & 1) * 32768u;

        // ---- S = Q K^T ----
        float s[8][4];
#pragma unroll
        for (int nt = 0; nt < 8; nt++)
#pragma unroll
            for (int i = 0; i < 4; i++) s[nt][i] = 0.f;

#pragma unroll
        for (int ks = 0; ks < 8; ks++) {
            unsigned int aqh[4], aql[4];
            const int cq = (2 * ks + (lane >> 4)) ^ (rloc & 7);
            const uint32_t qa = sb + (uint32_t)(rloc * 256 + cq * 16);
            ldm4u(aqh, qa);
            ldm4u(aql, qa + 32768);
#pragma unroll
            for (int ng = 0; ng < 4; ng++) {
                const int rn = ng * 16 + (lane & 15);
                const int cn = (2 * ks + (lane >> 4)) ^ (rn & 7);
                const uint32_t ka = kb + (uint32_t)(rn * 256 + cn * 16);
                unsigned int r[4];
                ldm4u(r, ka);
                unsigned int b0[2] = { r[0], r[2] };
                unsigned int b1[2] = { r[1], r[3] };
                mma16816(s[2 * ng],     aqh, b0);
                mma16816(s[2 * ng],     aql, b0);
                mma16816(s[2 * ng + 1], aqh, b1);
                mma16816(s[2 * ng + 1], aql, b1);
            }
        }

        // ---- scale + causal mask + online softmax ----
        float mx0 = -1e30f, mx1 = -1e30f;
#pragma unroll
        for (int nt = 0; nt < 8; nt++) {
            const int col = j * 64 + nt * 8 + (lane & 3) * 2;
            s[nt][0] = (col     <= rowg)     ? s[nt][0] * iscale : -1e30f;
            s[nt][1] = (col + 1 <= rowg)     ? s[nt][1] * iscale : -1e30f;
            s[nt][2] = (col     <= rowg + 8) ? s[nt][2] * iscale : -1e30f;
            s[nt][3] = (col + 1 <= rowg + 8) ? s[nt][3] * iscale : -1e30f;
            mx0 = fmaxf(mx0, fmaxf(s[nt][0], s[nt][1]));
            mx1 = fmaxf(mx1, fmaxf(s[nt][2], s[nt][3]));
        }
        mx0 = fmaxf(mx0, __shfl_xor_sync(0xffffffffu, mx0, 1));
        mx0 = fmaxf(mx0, __shfl_xor_sync(0xffffffffu, mx0, 2));
        mx1 = fmaxf(mx1, __shfl_xor_sync(0xffffffffu, mx1, 1));
        mx1 = fmaxf(mx1, __shfl_xor_sync(0xffffffffu, mx1, 2));
        const float nm0 = fmaxf(m0, mx0);
        const float nm1 = fmaxf(m1, mx1);
        const float al0 = __expf(m0 - nm0);
        const float al1 = __expf(m1 - nm1);
        m0 = nm0; m1 = nm1;

        float sum0 = 0.f, sum1 = 0.f;
#pragma unroll
        for (int nt = 0; nt < 8; nt++) {
            s[nt][0] = __expf(s[nt][0] - nm0);
            s[nt][1] = __expf(s[nt][1] - nm0);
            s[nt][2] = __expf(s[nt][2] - nm1);
            s[nt][3] = __expf(s[nt][3] - nm1);
            sum0 += s[nt][0] + s[nt][1];
            sum1 += s[nt][2] + s[nt][3];
        }
        sum0 += __shfl_xor_sync(0xffffffffu, sum0, 1);
        sum0 += __shfl_xor_sync(0xffffffffu, sum0, 2);
        sum1 += __shfl_xor_sync(0xffffffffu, sum1, 1);
        sum1 += __shfl_xor_sync(0xffffffffu, sum1, 2);
        l0 = l0 * al0 + sum0;
        l1 = l1 * al1 + sum1;

#pragma unroll
        for (int nt = 0; nt < 16; nt++) {
            o[nt][0] *= al0; o[nt][1] *= al0;
            o[nt][2] *= al1; o[nt][3] *= al1;
        }

        // ---- PV ----
#pragma unroll
        for (int ks = 0; ks < 4; ks++) {
            unsigned int ph[4], pl[4];
            ph[0] = pack_hilo_h(s[2 * ks][0],     s[2 * ks][1],     &pl[0]);
            ph[1] = pack_hilo_h(s[2 * ks][2],     s[2 * ks][3],     &pl[1]);
            ph[2] = pack_hilo_h(s[2 * ks + 1][0], s[2 * ks + 1][1], &pl[2]);
            ph[3] = pack_hilo_h(s[2 * ks + 1][2], s[2 * ks + 1][3], &pl[3]);
#pragma unroll
            for (int ng = 0; ng < 8; ng++) {
                const int kr = ks * 16 + (lane & 15);
                const int cv = (ng * 2 + (lane >> 4)) ^ (kr & 7);
                const uint32_t va = kb + 16384u + (uint32_t)(kr * 256 + cv * 16);
                unsigned int r[4];
                ldm4tu(r, va);
                unsigned int b0[2] = { r[0], r[1] };
                unsigned int b1[2] = { r[2], r[3] };
                mma16816(o[2 * ng],     ph, b0);
                mma16816(o[2 * ng],     pl, b0);
                mma16816(o[2 * ng + 1], ph, b1);
                mma16816(o[2 * ng + 1], pl, b1);
            }
        }
    }

    const float inv0 = 1.f / l0;
    const float inv1 = 1.f / l1;
#pragma unroll
    for (int nt = 0; nt < 16; nt++) {
        const int c = hd0 + nt * 8 + (lane & 3) * 2;
        unsigned lo, hi;
        hi = pack_hilo_h(o[nt][0] * inv0, o[nt][1] * inv0, &lo);
        *reinterpret_cast<unsigned*>(ath + (size_t)rowg * D + c) = hi;
        *reinterpret_cast<unsigned*>(atl + (size_t)rowg * D + c) = lo;
        hi = pack_hilo_h(o[nt][2] * inv1, o[nt][3] * inv1, &lo);
        *reinterpret_cast<unsigned*>(ath + (size_t)(rowg + 8) * D + c) = hi;
        *reinterpret_cast<unsigned*>(atl + (size_t)(rowg + 8) * D + c) = lo;
    }
}

// ---------------- elementwise kernels --------------------------------------
// weights: hi only
__global__ __launch_bounds__(256) void split_pack_h(
    const float* __restrict__ in, hlf* __restrict__ hi,
    int nsrc, int ndst, int coff)
{
    const size_t i4 = (size_t)blockIdx.x * 256 + threadIdx.x;
    const size_t e  = i4 * 4;
    const size_t row = e / nsrc;
    const size_t col = e % nsrc;
    const float4 v = reinterpret_cast<const float4*>(in)[i4];
    const size_t o2 = (row * ndst + coff + col) / 2;
    __half2 a = __floats2half2_rn(v.x, v.y);
    __half2 b = __floats2half2_rn(v.z, v.w);
    reinterpret_cast<unsigned*>(hi)[o2]     = *reinterpret_cast<unsigned*>(&a);
    reinterpret_cast<unsigned*>(hi)[o2 + 1] = *reinterpret_cast<unsigned*>(&b);
}

__global__ __launch_bounds__(256) void rmsnorm_split_h(
    const float* __restrict__ x, const float* __restrict__ w,
    hlf* __restrict__ hi, hlf* __restrict__ lo)
{
    const int row = blockIdx.x;
    const float4* xr = reinterpret_cast<const float4*>(x + (size_t)row * D);
    float4 va[2];
    float ss = 0.f;
#pragma unroll
    for (int i = 0; i < 2; i++) {
        va[i] = xr[threadIdx.x + i * 256];
        ss += va[i].x * va[i].x + va[i].y * va[i].y +
              va[i].z * va[i].z + va[i].w * va[i].w;
    }
    __shared__ float red[256];
    red[threadIdx.x] = ss;
    __syncthreads();
    for (int s = 128; s > 0; s >>= 1) {
        if (threadIdx.x < s) red[threadIdx.x] += red[threadIdx.x + s];
        __syncthreads();
    }
    const float r = rsqrtf(red[0] * (1.0f / D) + EPS);
    const float4* w4 = reinterpret_cast<const float4*>(w);
#pragma unroll
    for (int i = 0; i < 2; i++) {
        const float4 wv = w4[threadIdx.x + i * 256];
        const size_t o2 = ((size_t)row * D) / 2 + (threadIdx.x + i * 256) * 2;
        unsigned l, h;
        h = pack_hilo_h(va[i].x * r * wv.x, va[i].y * r * wv.y, &l);
        reinterpret_cast<unsigned*>(hi)[o2]     = h;
        reinterpret_cast<unsigned*>(lo)[o2]     = l;
        h = pack_hilo_h(va[i].z * r * wv.z, va[i].w * r * wv.w, &l);
        reinterpret_cast<unsigned*>(hi)[o2 + 1] = h;
        reinterpret_cast<unsigned*>(lo)[o2 + 1] = l;
    }
}

// rope+split q (hi/lo), rope k (hi), v (hi) — from packed qkv fp32 [S, 3D]
__global__ __launch_bounds__(256) void qkv_post_h(
    const float* __restrict__ qkv,
    const float* __restrict__ cs, const float* __restrict__ sn,
    hlf* __restrict__ qh, hlf* __restrict__ ql,
    hlf* __restrict__ kh, hlf* __restrict__ vh)
{
    const int idx = blockIdx.x * 256 + threadIdx.x;   // over S*D/2
    const int s   = idx / (D / 2);
    const int rem = idx % (D / 2);
    const int h   = rem >> 6;
    const int d   = rem & 63;
    const size_t pq0 = (size_t)s * (3 * D) + h * HD + d;
    const size_t pq1 = pq0 + 64;
    const size_t po0 = (size_t)s * D + h * HD + d;
    const size_t po1 = po0 + 64;
    const float c0 = cs[s * HD + d],      s0 = sn[s * HD + d];
    const float c1 = cs[s * HD + d + 64], s1 = sn[s * HD + d + 64];

    hlf hh, ll;
    const float q0 = qkv[pq0], q1 = qkv[pq1];
    split1h(q0 * c0 - q1 * s0, &hh, &ll); qh[po0] = hh; ql[po0] = ll;
    split1h(q1 * c1 + q0 * s1, &hh, &ll); qh[po1] = hh; ql[po1] = ll;
    const float k0 = qkv[pq0 + D], k1 = qkv[pq1 + D];
    kh[po0] = __float2half_rn(k0 * c0 - k1 * s0);
    kh[po1] = __float2half_rn(k1 * c1 + k0 * s1);
    vh[po0] = __float2half_rn(qkv[pq0 + 2 * D]);
    vh[po1] = __float2half_rn(qkv[pq1 + 2 * D]);
}

// silu(h13[:, :I]) * h13[:, I:] -> hi/lo
__global__ __launch_bounds__(256) void silu_split_h(
    const float* __restrict__ h13, hlf* __restrict__ gh, hlf* __restrict__ gl)
{
    const size_t i4  = (size_t)blockIdx.x * 256 + threadIdx.x;  // over S*I/4
    const size_t row = i4 / (II / 4);
    const size_t c4  = (i4 % (II / 4)) * 4;
    const size_t b   = row * (2 * II) + c4;
    const float4 a = *reinterpret_cast<const float4*>(h13 + b);
    const float4 g = *reinterpret_cast<const float4*>(h13 + b + II);
    float4 o;
    o.x = a.x / (1.f + __expf(-a.x)) * g.x;
    o.y = a.y / (1.f + __expf(-a.y)) * g.y;
    o.z = a.z / (1.f + __expf(-a.z)) * g.z;
    o.w = a.w / (1.f + __expf(-a.w)) * g.w;
    const size_t o2 = (row * II + c4) / 2;
    unsigned l, h;
    h = pack_hilo_h(o.x, o.y, &l);
    reinterpret_cast<unsigned*>(gh)[o2]     = h;
    reinterpret_cast<unsigned*>(gl)[o2]     = l;
    h = pack_hilo_h(o.z, o.w, &l);
    reinterpret_cast<unsigned*>(gh)[o2 + 1] = h;
    reinterpret_cast<unsigned*>(gl)[o2 + 1] = l;
}

// ---------------- launch ---------------------------------------------------
extern "C" void kernel_launch(void* const* d_in, const int* in_sizes, int n_in,
                              void* d_out, int out_size)
{
    const float* x    = (const float*)d_in[0];
    const float* fcos = (const float*)d_in[2];
    const float* fsin = (const float*)d_in[3];
    const float* wq   = (const float*)d_in[4];
    const float* wk   = (const float*)d_in[5];
    const float* wv   = (const float*)d_in[6];
    const float* wo   = (const float*)d_in[7];
    const float* w1   = (const float*)d_in[8];
    const float* w2   = (const float*)d_in[9];
    const float* w3   = (const float*)d_in[10];
    const float* anw  = (const float*)d_in[11];
    const float* fnw  = (const float*)d_in[12];
    float* out = (float*)d_out;

    float *qkvf, *x1, *h13;
    hlf *nxh, *nxl, *qh, *ql, *kh, *vh, *ath, *atl;
    hlf *nx2h, *nx2l, *gh, *gl;
    hlf *wqkvh, *woh, *w13h, *w2h;

    cudaGetSymbolAddress((void**)&qkvf, g_qkvf);
    cudaGetSymbolAddress((void**)&x1,   g_x1);
    cudaGetSymbolAddress((void**)&h13,  g_h13);
    cudaGetSymbolAddress((void**)&nxh,  g_nxh);   cudaGetSymbolAddress((void**)&nxl,  g_nxl);
    cudaGetSymbolAddress((void**)&qh,   g_qh);    cudaGetSymbolAddress((void**)&ql,   g_ql);
    cudaGetSymbolAddress((void**)&kh,   g_kh);    cudaGetSymbolAddress((void**)&vh,   g_vh);
    cudaGetSymbolAddress((void**)&ath,  g_ath);   cudaGetSymbolAddress((void**)&atl,  g_atl);
    cudaGetSymbolAddress((void**)&nx2h, g_nx2h);  cudaGetSymbolAddress((void**)&nx2l, g_nx2l);
    cudaGetSymbolAddress((void**)&gh,   g_gh);    cudaGetSymbolAddress((void**)&gl,   g_gl);
    cudaGetSymbolAddress((void**)&wqkvh, g_wqkvh);
    cudaGetSymbolAddress((void**)&woh,  g_woh);
    cudaGetSymbolAddress((void**)&w13h, g_w13h);
    cudaGetSymbolAddress((void**)&w2h,  g_w2h);

    cudaFuncSetAttribute(tc7_gemm,
        cudaFuncAttributeMaxDynamicSharedMemorySize, GSMEM);
    cudaFuncSetAttribute(flash_attn,
        cudaFuncAttributeMaxDynamicSharedMemorySize, FSMEM);

    const dim3 gQkv(3 * D / 128, S / 128);       // 48x16
    const dim3 gProj(D / 128, S / 128);          // 16x16
    const dim3 gW13(2 * II / 128, S / 128);      // 128x16
    const dim3 gFa (S / 128, H);                 // 16x16

    const int nDD = (D * D) / 1024;
    const int nDI = (D * II) / 1024;

    // weight packs (hi only)
    split_pack_h<<<nDD, 256>>>(wq, wqkvh, D, 3 * D, 0);
    split_pack_h<<<nDD, 256>>>(wk, wqkvh, D, 3 * D, D);
    split_pack_h<<<nDD, 256>>>(wv, wqkvh, D, 3 * D, 2 * D);
    split_pack_h<<<nDD, 256>>>(wo, woh, D, D, 0);
    split_pack_h<<<nDI, 256>>>(w1, w13h, II, 2 * II, 0);
    split_pack_h<<<nDI, 256>>>(w3, w13h, II, 2 * II, II);
    split_pack_h<<<nDI, 256>>>(w2, w2h, D, D, 0);

    rmsnorm_split_h<<<S, 256>>>(x, anw, nxh, nxl);

    tc7_gemm<<<gQkv, 256, GSMEM>>>(nxh, nxl, D, wqkvh, 3 * D,
                                   nullptr, 0, qkvf, 3 * D, D);

    qkv_post_h<<<(S * D / 2) / 256, 256>>>(qkvf, fcos, fsin, qh, ql, kh, vh);

    flash_attn<<<gFa, 256, FSMEM>>>(qh, ql, kh, vh, ath, atl);

    tc7_gemm<<<gProj, 256, GSMEM>>>(ath, atl, D, woh, D,
                                    x, D, x1, D, D);

    rmsnorm_split_h<<<S, 256>>>(x1, fnw, nx2h, nx2l);

    tc7_gemm<<<gW13, 256, GSMEM>>>(nx2h, nx2l, D, w13h, 2 * II,
                                   nullptr, 0, h13, 2 * II, D);

    silu_split_h<<<(S * (size_t)II / 4) / 256, 256>>>(h13, gh, gl);

    tc7_gemm<<<gProj, 256, GSMEM>>>(gh, gl, II, w2h, D,
                                    x1, D, out, D, II);
}

// round 9
// speedup vs baseline: 7.9800x; 1.8339x over previous
#include <cuda_runtime.h>
#include <cuda_fp16.h>
#include <stdint.h>
#include <math.h>

#define S 2048
#define D 2048
#define H 16
#define HD 128
#define II 8192
#define EPS 1e-5f

typedef __half hlf;

// ---------------- scratch (static device globals; no allocation) ----------
__device__ float g_qkvf[(size_t)S * 3 * D];
__device__ float g_x1  [(size_t)S * D];
__device__ float g_h13 [(size_t)S * 2 * II];
__device__ hlf g_nxh [(size_t)S * D];
__device__ hlf g_qh  [(size_t)S * D];
__device__ hlf g_kh  [(size_t)S * D];
__device__ hlf g_vh  [(size_t)S * D];
__device__ hlf g_ath [(size_t)S * D];
__device__ hlf g_nx2h[(size_t)S * D];
__device__ hlf g_gh  [(size_t)S * II];
__device__ hlf g_wqkvh[(size_t)D * 3 * D];
__device__ hlf g_woh [(size_t)D * D];
__device__ hlf g_w13h[(size_t)D * 2 * II];
__device__ hlf g_w2h [(size_t)II * D];

// ---------------- PTX helpers ---------------------------------------------
__device__ __forceinline__ uint32_t smem_u32(const void* p)
{
    uint32_t a;
    asm("{ .reg .u64 t; cvta.to.shared.u64 t, %1; cvt.u32.u64 %0, t; }"
        : "=r"(a) : "l"(p));
    return a;
}

__device__ __forceinline__ void cpa16(uint32_t dst, const void* src)
{
    asm volatile("cp.async.cg.shared.global [%0], [%1], 16;"
                 :: "r"(dst), "l"(src));
}
#define CPA_COMMIT() asm volatile("cp.async.commit_group;" ::: "memory")
#define CPA_WAIT(n)  asm volatile("cp.async.wait_group %0;" :: "n"(n) : "memory")

__device__ __forceinline__ void ldm4u(unsigned int* r, uint32_t a)
{
    asm volatile("ldmatrix.sync.aligned.m8n8.x4.shared.b16 {%0,%1,%2,%3},[%4];"
                 : "=r"(r[0]), "=r"(r[1]), "=r"(r[2]), "=r"(r[3]) : "r"(a));
}
__device__ __forceinline__ void ldm4tu(unsigned int* r, uint32_t a)
{
    asm volatile("ldmatrix.sync.aligned.m8n8.x4.trans.shared.b16 {%0,%1,%2,%3},[%4];"
                 : "=r"(r[0]), "=r"(r[1]), "=r"(r[2]), "=r"(r[3]) : "r"(a));
}
__device__ __forceinline__ void mma16816(float* d, const unsigned int* a,
                                         const unsigned int* b)
{
    asm volatile(
        "mma.sync.aligned.m16n8k16.row.col.f32.f16.f16.f32 "
        "{%0,%1,%2,%3},{%4,%5,%6,%7},{%8,%9},{%0,%1,%2,%3};"
        : "+f"(d[0]), "+f"(d[1]), "+f"(d[2]), "+f"(d[3])
        : "r"(a[0]), "r"(a[1]), "r"(a[2]), "r"(a[3]), "r"(b[0]), "r"(b[1]));
}

__device__ __forceinline__ unsigned pack_h2(float a, float b)
{
    __half2 t = __floats2half2_rn(a, b);
    return *reinterpret_cast<unsigned*>(&t);
}

// ---------------- fp16 GEMM, cp.async 3-stage pipeline, k64 chunks ---------
// C[128,128] = A[M,K] * B[K,N] (+Res). All NN, fp32 accum.
// Stage 32KB: A 128x64 @0, B 64x128 @16384 (two 8K n-halves).
#define STG 32768
#define GSMEM (3 * STG)

__device__ __forceinline__ void stage8(
    uint32_t sb,
    const hlf* __restrict__ Ah, int lda,
    const hlf* __restrict__ Bh, int ldb,
    int row0, int col0, int k0, int tid)
{
#pragma unroll
    for (int j = 0; j < 4; j++) {
        const int id = tid + j * 256;
        const int r = id >> 3, c = id & 7;
        const uint32_t off = (uint32_t)(r * 128 + ((c ^ (r & 7)) * 16));
        cpa16(sb + off, Ah + (size_t)(row0 + r) * lda + k0 + c * 8);
    }
#pragma unroll
    for (int j = 0; j < 4; j++) {
        const int id = tid + j * 256;
        const int r = id >> 4, c = id & 15;
        const int sub = c >> 3;
        const uint32_t off = (uint32_t)(16384 + sub * 8192 + r * 128
                                        + (((c & 7) ^ (r & 7)) * 16));
        cpa16(sb + off, Bh + (size_t)(k0 + r) * ldb + col0 + c * 8);
    }
}

__global__ void __launch_bounds__(256) tc8_gemm(
    const hlf* __restrict__ Ah, int lda,
    const hlf* __restrict__ Bh, int ldb,
    const float* __restrict__ Res, int ldres,
    float* __restrict__ Cf, int ldc, int K)
{
    extern __shared__ char smem[];
    const uint32_t sbase = smem_u32(smem);

    const int tid  = threadIdx.x;
    const int lane = tid & 31;
    const int wid  = tid >> 5;
    const int wm   = wid >> 1;
    const int wn   = wid & 1;
    const int row0 = blockIdx.y * 128;
    const int col0 = blockIdx.x * 128;

    const int nch = K >> 6;

    float acc[2][8][4];
#pragma unroll
    for (int m = 0; m < 2; m++)
#pragma unroll
        for (int n = 0; n < 8; n++)
#pragma unroll
            for (int i = 0; i < 4; i++) acc[m][n][i] = 0.f;

    stage8(sbase, Ah, lda, Bh, ldb, row0, col0, 0, tid);
    CPA_COMMIT();
    stage8(sbase + STG, Ah, lda, Bh, ldb, row0, col0, 64, tid);
    CPA_COMMIT();

    for (int ch = 0; ch < nch; ch++) {
        if (ch + 1 < nch) { CPA_WAIT(1); } else { CPA_WAIT(0); }
        __syncthreads();

        if (ch + 2 < nch) {
            stage8(sbase + ((ch + 2) % 3) * STG, Ah, lda, Bh, ldb,
                   row0, col0, (ch + 2) * 64, tid);
            CPA_COMMIT();
        }

        const uint32_t base = sbase + (ch % 3) * STG;

#pragma unroll
        for (int kk = 0; kk < 64; kk += 16) {
            unsigned int ah[2][4];
#pragma unroll
            for (int mt = 0; mt < 2; mt++) {
                const int m  = wm * 32 + mt * 16 + (lane & 15);
                const int cc = ((kk >> 3) + (lane >> 4)) ^ (m & 7);
                ldm4u(ah[mt], base + (uint32_t)(m * 128 + cc * 16));
            }
#pragma unroll
            for (int g = 0; g < 4; g++) {
                const int kr = kk + (lane & 15);
                const int c  = wn * 8 + g * 2 + (lane >> 4);
                const int sub = c >> 3;
                const int cw  = (c & 7) ^ (kr & 7);
                const uint32_t a = base + 16384u
                    + (uint32_t)(sub * 8192 + kr * 128 + cw * 16);
                unsigned int r4[4];
                ldm4tu(r4, a);
                unsigned int b0[2] = { r4[0], r4[1] };
                unsigned int b1[2] = { r4[2], r4[3] };
#pragma unroll
                for (int mt = 0; mt < 2; mt++) {
                    mma16816(acc[mt][2 * g],     ah[mt], b0);
                    mma16816(acc[mt][2 * g + 1], ah[mt], b1);
                }
            }
        }
    }

#pragma unroll
    for (int mt = 0; mt < 2; mt++) {
        const int r0 = row0 + wm * 32 + mt * 16 + (lane >> 2);
#pragma unroll
        for (int nt = 0; nt < 8; nt++) {
            const int c = col0 + wn * 64 + nt * 8 + (lane & 3) * 2;
            float2 v0 = make_float2(acc[mt][nt][0], acc[mt][nt][1]);
            float2 v1 = make_float2(acc[mt][nt][2], acc[mt][nt][3]);
            if (Res) {
                const float2 q0 = *reinterpret_cast<const float2*>(
                    Res + (size_t)r0 * ldres + c);
                const float2 q1 = *reinterpret_cast<const float2*>(
                    Res + (size_t)(r0 + 8) * ldres + c);
                v0.x += q0.x; v0.y += q0.y; v1.x += q1.x; v1.y += q1.y;
            }
            *reinterpret_cast<float2*>(Cf + (size_t)r0 * ldc + c) = v0;
            *reinterpret_cast<float2*>(Cf + (size_t)(r0 + 8) * ldc + c) = v1;
        }
    }
}

// ---------------- flash attention (fp16) ------------------------------------
// smem: Qh[32K]@0; stage b at 32768+b*32768: Kh+0, Vh+16384.
#define FSMEM (32768 + 2 * 32768)

__device__ __forceinline__ void fa_stage_kv(
    uint32_t dst, const hlf* __restrict__ kh, const hlf* __restrict__ vh,
    int krow0, int hd0, int tid)
{
#pragma unroll
    for (int j = 0; j < 4; j++) {
        const int id = tid + j * 256;
        const int r = id >> 4, c = id & 15;
        const uint32_t off = (uint32_t)(r * 256 + ((c ^ (r & 7)) * 16));
        const size_t g = (size_t)(krow0 + r) * D + hd0 + c * 8;
        cpa16(dst + off, kh + g);
        cpa16(dst + 16384 + off, vh + g);
    }
}

__global__ void __launch_bounds__(256, 1) flash_attn(
    const hlf* __restrict__ qh, const hlf* __restrict__ kh,
    const hlf* __restrict__ vh, hlf* __restrict__ ath)
{
    extern __shared__ char smem[];
    const uint32_t sb = smem_u32(smem);
    const int qb  = gridDim.x - 1 - blockIdx.x;   // heavy blocks first
    const int hd0 = blockIdx.y * HD;
    const int q0  = qb * 128;
    const int tid = threadIdx.x, lane = tid & 31, w = tid >> 5;
    const float iscale = 0.08838834764831845f;    // 1/sqrt(128)

#pragma unroll
    for (int j = 0; j < 8; j++) {
        const int id = tid + j * 256;
        const int r = id >> 4, c = id & 15;
        const uint32_t off = (uint32_t)(r * 256 + ((c ^ (r & 7)) * 16));
        cpa16(sb + off, qh + (size_t)(q0 + r) * D + hd0 + c * 8);
    }
    fa_stage_kv(sb + 32768, kh, vh, 0, hd0, tid);
    CPA_COMMIT();

    const int nkt = 2 * (qb + 1);

    float m0 = -1e30f, m1 = -1e30f, l0 = 0.f, l1 = 0.f;
    float o[16][4];
#pragma unroll
    for (int nt = 0; nt < 16; nt++)
#pragma unroll
        for (int i = 0; i < 4; i++) o[nt][i] = 0.f;

    const int rloc = w * 16 + (lane & 15);
    const int rowg = q0 + w * 16 + (lane >> 2);

    for (int j = 0; j < nkt; j++) {
        __syncthreads();
        if (j + 1 < nkt) {
            fa_stage_kv(sb + 32768u + ((j + 1) & 1) * 32768u,
                        kh, vh, (j + 1) * 64, hd0, tid);
            CPA_COMMIT();
            CPA_WAIT(1);
        } else {
            CPA_WAIT(0);
        }
        __syncthreads();

        const uint32_t kb = sb + 32768u + (j & 1) * 32768u;

        // ---- S = Q K^T ----
        float s[8][4];
#pragma unroll
        for (int nt = 0; nt < 8; nt++)
#pragma unroll
            for (int i = 0; i < 4; i++) s[nt][i] = 0.f;

#pragma unroll
        for (int ks = 0; ks < 8; ks++) {
            unsigned int aq[4];
            const int cq = (2 * ks + (lane >> 4)) ^ (rloc & 7);
            ldm4u(aq, sb + (uint32_t)(rloc * 256 + cq * 16));
#pragma unroll
            for (int ng = 0; ng < 4; ng++) {
                const int rn = ng * 16 + (lane & 15);
                const int cn = (2 * ks + (lane >> 4)) ^ (rn & 7);
                unsigned int r[4];
                ldm4u(r, kb + (uint32_t)(rn * 256 + cn * 16));
                unsigned int b0[2] = { r[0], r[2] };
                unsigned int b1[2] = { r[1], r[3] };
                mma16816(s[2 * ng],     aq, b0);
                mma16816(s[2 * ng + 1], aq, b1);
            }
        }

        // ---- scale + causal mask + online softmax ----
        float mx0 = -1e30f, mx1 = -1e30f;
#pragma unroll
        for (int nt = 0; nt < 8; nt++) {
            const int col = j * 64 + nt * 8 + (lane & 3) * 2;
            s[nt][0] = (col     <= rowg)     ? s[nt][0] * iscale : -1e30f;
            s[nt][1] = (col + 1 <= rowg)     ? s[nt][1] * iscale : -1e30f;
            s[nt][2] = (col     <= rowg + 8) ? s[nt][2] * iscale : -1e30f;
            s[nt][3] = (col + 1 <= rowg + 8) ? s[nt][3] * iscale : -1e30f;
            mx0 = fmaxf(mx0, fmaxf(s[nt][0], s[nt][1]));
            mx1 = fmaxf(mx1, fmaxf(s[nt][2], s[nt][3]));
        }
        mx0 = fmaxf(mx0, __shfl_xor_sync(0xffffffffu, mx0, 1));
        mx0 = fmaxf(mx0, __shfl_xor_sync(0xffffffffu, mx0, 2));
        mx1 = fmaxf(mx1, __shfl_xor_sync(0xffffffffu, mx1, 1));
        mx1 = fmaxf(mx1, __shfl_xor_sync(0xffffffffu, mx1, 2));
        const float nm0 = fmaxf(m0, mx0);
        const float nm1 = fmaxf(m1, mx1);
        const float al0 = __expf(m0 - nm0);
        const float al1 = __expf(m1 - nm1);
        m0 = nm0; m1 = nm1;

        float sum0 = 0.f, sum1 = 0.f;
#pragma unroll
        for (int nt = 0; nt < 8; nt++) {
            s[nt][0] = __expf(s[nt][0] - nm0);
            s[nt][1] = __expf(s[nt][1] - nm0);
            s[nt][2] = __expf(s[nt][2] - nm1);
            s[nt][3] = __expf(s[nt][3] - nm1);
            sum0 += s[nt][0] + s[nt][1];
            sum1 += s[nt][2] + s[nt][3];
        }
        sum0 += __shfl_xor_sync(0xffffffffu, sum0, 1);
        sum0 += __shfl_xor_sync(0xffffffffu, sum0, 2);
        sum1 += __shfl_xor_sync(0xffffffffu, sum1, 1);
        sum1 += __shfl_xor_sync(0xffffffffu, sum1, 2);
        l0 = l0 * al0 + sum0;
        l1 = l1 * al1 + sum1;

#pragma unroll
        for (int nt = 0; nt < 16; nt++) {
            o[nt][0] *= al0; o[nt][1] *= al0;
            o[nt][2] *= al1; o[nt][3] *= al1;
        }

        // ---- PV ----
#pragma unroll
        for (int ks = 0; ks < 4; ks++) {
            unsigned int ph[4];
            ph[0] = pack_h2(s[2 * ks][0],     s[2 * ks][1]);
            ph[1] = pack_h2(s[2 * ks][2],     s[2 * ks][3]);
            ph[2] = pack_h2(s[2 * ks + 1][0], s[2 * ks + 1][1]);
            ph[3] = pack_h2(s[2 * ks + 1][2], s[2 * ks + 1][3]);
#pragma unroll
            for (int ng = 0; ng < 8; ng++) {
                const int kr = ks * 16 + (lane & 15);
                const int cv = (ng * 2 + (lane >> 4)) ^ (kr & 7);
                unsigned int r[4];
                ldm4tu(r, kb + 16384u + (uint32_t)(kr * 256 + cv * 16));
                unsigned int b0[2] = { r[0], r[1] };
                unsigned int b1[2] = { r[2], r[3] };
                mma16816(o[2 * ng],     ph, b0);
                mma16816(o[2 * ng + 1], ph, b1);
            }
        }
    }

    const float inv0 = 1.f / l0;
    const float inv1 = 1.f / l1;
#pragma unroll
    for (int nt = 0; nt < 16; nt++) {
        const int c = hd0 + nt * 8 + (lane & 3) * 2;
        *reinterpret_cast<unsigned*>(ath + (size_t)rowg * D + c) =
            pack_h2(o[nt][0] * inv0, o[nt][1] * inv0);
        *reinterpret_cast<unsigned*>(ath + (size_t)(rowg + 8) * D + c) =
            pack_h2(o[nt][2] * inv1, o[nt][3] * inv1);
    }
}

// ---------------- elementwise kernels --------------------------------------
__global__ __launch_bounds__(256) void split_pack_h(
    const float* __restrict__ in, hlf* __restrict__ hi,
    int nsrc, int ndst, int coff)
{
    const size_t i4 = (size_t)blockIdx.x * 256 + threadIdx.x;
    const size_t e  = i4 * 4;
    const size_t row = e / nsrc;
    const size_t col = e % nsrc;
    const float4 v = reinterpret_cast<const float4*>(in)[i4];
    const size_t o2 = (row * ndst + coff + col) / 2;
    reinterpret_cast<unsigned*>(hi)[o2]     = pack_h2(v.x, v.y);
    reinterpret_cast<unsigned*>(hi)[o2 + 1] = pack_h2(v.z, v.w);
}

__global__ __launch_bounds__(256) void rmsnorm_h(
    const float* __restrict__ x, const float* __restrict__ w,
    hlf* __restrict__ hi)
{
    const int row = blockIdx.x;
    const float4* xr = reinterpret_cast<const float4*>(x + (size_t)row * D);
    float4 va[2];
    float ss = 0.f;
#pragma unroll
    for (int i = 0; i < 2; i++) {
        va[i] = xr[threadIdx.x + i * 256];
        ss += va[i].x * va[i].x + va[i].y * va[i].y +
              va[i].z * va[i].z + va[i].w * va[i].w;
    }
    __shared__ float red[256];
    red[threadIdx.x] = ss;
    __syncthreads();
    for (int s = 128; s > 0; s >>= 1) {
        if (threadIdx.x < s) red[threadIdx.x] += red[threadIdx.x + s];
        __syncthreads();
    }
    const float r = rsqrtf(red[0] * (1.0f / D) + EPS);
    const float4* w4 = reinterpret_cast<const float4*>(w);
#pragma unroll
    for (int i = 0; i < 2; i++) {
        const float4 wv = w4[threadIdx.x + i * 256];
        const size_t o2 = ((size_t)row * D) / 2 + (threadIdx.x + i * 256) * 2;
        reinterpret_cast<unsigned*>(hi)[o2] =
            pack_h2(va[i].x * r * wv.x, va[i].y * r * wv.y);
        reinterpret_cast<unsigned*>(hi)[o2 + 1] =
            pack_h2(va[i].z * r * wv.z, va[i].w * r * wv.w);
    }
}

__global__ __launch_bounds__(256) void qkv_post_h(
    const float* __restrict__ qkv,
    const float* __restrict__ cs, const float* __restrict__ sn,
    hlf* __restrict__ qh, hlf* __restrict__ kh, hlf* __restrict__ vh)
{
    const int idx = blockIdx.x * 256 + threadIdx.x;   // over S*D/2
    const int s   = idx / (D / 2);
    const int rem = idx % (D / 2);
    const int h   = rem >> 6;
    const int d   = rem & 63;
    const size_t pq0 = (size_t)s * (3 * D) + h * HD + d;
    const size_t pq1 = pq0 + 64;
    const size_t po0 = (size_t)s * D + h * HD + d;
    const size_t po1 = po0 + 64;
    const float c0 = cs[s * HD + d],      s0 = sn[s * HD + d];
    const float c1 = cs[s * HD + d + 64], s1 = sn[s * HD + d + 64];

    const float q0 = qkv[pq0], q1 = qkv[pq1];
    qh[po0] = __float2half_rn(q0 * c0 - q1 * s0);
    qh[po1] = __float2half_rn(q1 * c1 + q0 * s1);
    const float k0 = qkv[pq0 + D], k1 = qkv[pq1 + D];
    kh[po0] = __float2half_rn(k0 * c0 - k1 * s0);
    kh[po1] = __float2half_rn(k1 * c1 + k0 * s1);
    vh[po0] = __float2half_rn(qkv[pq0 + 2 * D]);
    vh[po1] = __float2half_rn(qkv[pq1 + 2 * D]);
}

__global__ __launch_bounds__(256) void silu_h(
    const float* __restrict__ h13, hlf* __restrict__ gh)
{
    const size_t i4  = (size_t)blockIdx.x * 256 + threadIdx.x;  // over S*I/4
    const size_t row = i4 / (II / 4);
    const size_t c4  = (i4 % (II / 4)) * 4;
    const size_t b   = row * (2 * II) + c4;
    const float4 a = *reinterpret_cast<const float4*>(h13 + b);
    const float4 g = *reinterpret_cast<const float4*>(h13 + b + II);
    float4 o;
    o.x = a.x / (1.f + __expf(-a.x)) * g.x;
    o.y = a.y / (1.f + __expf(-a.y)) * g.y;
    o.z = a.z / (1.f + __expf(-a.z)) * g.z;
    o.w = a.w / (1.f + __expf(-a.w)) * g.w;
    const size_t o2 = (row * II + c4) / 2;
    reinterpret_cast<unsigned*>(gh)[o2]     = pack_h2(o.x, o.y);
    reinterpret_cast<unsigned*>(gh)[o2 + 1] = pack_h2(o.z, o.w);
}

// ---------------- launch ---------------------------------------------------
extern "C" void kernel_launch(void* const* d_in, const int* in_sizes, int n_in,
                              void* d_out, int out_size)
{
    const float* x    = (const float*)d_in[0];
    const float* fcos = (const float*)d_in[2];
    const float* fsin = (const float*)d_in[3];
    const float* wq   = (const float*)d_in[4];
    const float* wk   = (const float*)d_in[5];
    const float* wv   = (const float*)d_in[6];
    const float* wo   = (const float*)d_in[7];
    const float* w1   = (const float*)d_in[8];
    const float* w2   = (const float*)d_in[9];
    const float* w3   = (const float*)d_in[10];
    const float* anw  = (const float*)d_in[11];
    const float* fnw  = (const float*)d_in[12];
    float* out = (float*)d_out;

    float *qkvf, *x1, *h13;
    hlf *nxh, *qh, *kh, *vh, *ath, *nx2h, *gh;
    hlf *wqkvh, *woh, *w13h, *w2h;

    cudaGetSymbolAddress((void**)&qkvf, g_qkvf);
    cudaGetSymbolAddress((void**)&x1,   g_x1);
    cudaGetSymbolAddress((void**)&h13,  g_h13);
    cudaGetSymbolAddress((void**)&nxh,  g_nxh);
    cudaGetSymbolAddress((void**)&qh,   g_qh);
    cudaGetSymbolAddress((void**)&kh,   g_kh);
    cudaGetSymbolAddress((void**)&vh,   g_vh);
    cudaGetSymbolAddress((void**)&ath,  g_ath);
    cudaGetSymbolAddress((void**)&nx2h, g_nx2h);
    cudaGetSymbolAddress((void**)&gh,   g_gh);
    cudaGetSymbolAddress((void**)&wqkvh, g_wqkvh);
    cudaGetSymbolAddress((void**)&woh,  g_woh);
    cudaGetSymbolAddress((void**)&w13h, g_w13h);
    cudaGetSymbolAddress((void**)&w2h,  g_w2h);

    cudaFuncSetAttribute(tc8_gemm,
        cudaFuncAttributeMaxDynamicSharedMemorySize, GSMEM);
    cudaFuncSetAttribute(flash_attn,
        cudaFuncAttributeMaxDynamicSharedMemorySize, FSMEM);

    const dim3 gQkv(3 * D / 128, S / 128);       // 48x16
    const dim3 gProj(D / 128, S / 128);          // 16x16
    const dim3 gW13(2 * II / 128, S / 128);      // 128x16
    const dim3 gFa (S / 128, H);                 // 16x16

    const int nDD = (D * D) / 1024;
    const int nDI = (D * II) / 1024;

    split_pack_h<<<nDD, 256>>>(wq, wqkvh, D, 3 * D, 0);
    split_pack_h<<<nDD, 256>>>(wk, wqkvh, D, 3 * D, D);
    split_pack_h<<<nDD, 256>>>(wv, wqkvh, D, 3 * D, 2 * D);
    split_pack_h<<<nDD, 256>>>(wo, woh, D, D, 0);
    split_pack_h<<<nDI, 256>>>(w1, w13h, II, 2 * II, 0);
    split_pack_h<<<nDI, 256>>>(w3, w13h, II, 2 * II, II);
    split_pack_h<<<nDI, 256>>>(w2, w2h, D, D, 0);

    rmsnorm_h<<<S, 256>>>(x, anw, nxh);

    tc8_gemm<<<gQkv, 256, GSMEM>>>(nxh, D, wqkvh, 3 * D,
                                   nullptr, 0, qkvf, 3 * D, D);

    qkv_post_h<<<(S * D / 2) / 256, 256>>>(qkvf, fcos, fsin, qh, kh, vh);

    flash_attn<<<gFa, 256, FSMEM>>>(qh, kh, vh, ath);

    tc8_gemm<<<gProj, 256, GSMEM>>>(ath, D, woh, D, x, D, x1, D, D);

    rmsnorm_h<<<S, 256>>>(x1, fnw, nx2h);

    tc8_gemm<<<gW13, 256, GSMEM>>>(nx2h, D, w13h, 2 * II,
                                   nullptr, 0, h13, 2 * II, D);

    silu_h<<<(S * (size_t)II / 4) / 256, 256>>>(h13, gh);

    tc8_gemm<<<gProj, 256, GSMEM>>>(gh, II, w2h, D, x1, D, out, D, II);
}